// round 1
// baseline (speedup 1.0000x reference)
#include <cuda_runtime.h>
#include <math.h>

#define BS 16
#define NCLS 80
#define REGM 16
#define NKPT 51
#define A_TOT 8400
#define MAX_DET 100
#define M_TOT 195
#define M_PAD 256
#define CONF 0.25f

// output layout (floats)
#define O_NUM   0
#define O_BOX   16
#define O_SCORE 6416
#define O_CLS   8016
#define O_KPT   9616

// scratch (device globals — no allocation allowed)
__device__ float g_wt[(128 + 256 + 512) * M_PAD];   // k-major packed weights, padded M=256
__device__ float g_bias[3 * M_PAD];
__device__ float g_out195[(size_t)BS * M_TOT * A_TOT];   // [b][m][a] ~105MB
__device__ float g_dbox[(size_t)BS * 4 * A_TOT];         // [b][4][a]
__device__ float g_kpts[(size_t)BS * NKPT * A_TOT];      // [b][nk][a]
__device__ float g_maxs[BS * A_TOT];
__device__ int   g_cls[BS * A_TOT];

// ---------------------------------------------------------------------------
// Pack weights for one scale: g_wt[(krow_off+k)*256 + m], m: [0,64)=cv2,
// [64,144)=cv3, [144,195)=cv4, rest zero. Bias likewise.
// ---------------------------------------------------------------------------
__global__ void pack_k(const float* __restrict__ w2, const float* __restrict__ b2,
                       const float* __restrict__ w3, const float* __restrict__ b3,
                       const float* __restrict__ w4, const float* __restrict__ b4,
                       int C, int krow_off, int s)
{
    int idx = blockIdx.x * blockDim.x + threadIdx.x;
    if (idx >= C * M_PAD) return;
    int k = idx / M_PAD;
    int m = idx - k * M_PAD;
    float v = 0.f;
    if (m < 64)        v = w2[m * C + k];
    else if (m < 144)  v = w3[(m - 64) * C + k];
    else if (m < 195)  v = w4[(m - 144) * C + k];
    g_wt[(size_t)(krow_off + k) * M_PAD + m] = v;
    if (k == 0) {
        float bb = 0.f;
        if (m < 64)        bb = b2[m];
        else if (m < 144)  bb = b3[m - 64];
        else if (m < 195)  bb = b4[m - 144];
        g_bias[s * M_PAD + m] = bb;
    }
}

// ---------------------------------------------------------------------------
// SGEMM: out195[b][m][scale_off+pos] = sum_k W[m][k] * x[b][k][pos] + bias
// BM=64 BN=128 BK=16, 256 threads, thread tile 4x8.
// Columns n_g = blockIdx.x*128 + n, b = n_g/HW, pos = n_g%HW.
// HW % 4 == 0 so float4 column groups never straddle a batch boundary.
// ---------------------------------------------------------------------------
__global__ void __launch_bounds__(256) gemm_k(const float* __restrict__ x,
                                              int C, int HW,
                                              int krow_off, int scale_off, int s)
{
    __shared__ float As[16][64];
    __shared__ float Bs[16][128];

    const int tid = threadIdx.x;
    const int tx = tid & 15;      // N dir
    const int ty = tid >> 4;      // M dir
    const int m_base = blockIdx.y * 64;
    const int n_base = blockIdx.x * 128;

    float acc[4][8];
#pragma unroll
    for (int i = 0; i < 4; i++)
#pragma unroll
        for (int j = 0; j < 8; j++) acc[i][j] = 0.f;

    const int nKt = C >> 4;
    for (int kt = 0; kt < nKt; ++kt) {
        // A tile: 16x64 = 1024 floats, 1 float4/thread
        {
            int k  = tid >> 4;
            int m4 = (tid & 15) * 4;
            *(float4*)&As[k][m4] =
                *(const float4*)&g_wt[(size_t)(krow_off + kt * 16 + k) * M_PAD + m_base + m4];
        }
        // B tile: 16x128 = 2048 floats, 2 float4/thread
#pragma unroll
        for (int i = 0; i < 2; i++) {
            int k  = (tid >> 5) + i * 8;
            int n4 = (tid & 31) * 4;
            int n_g = n_base + n4;
            int b   = n_g / HW;
            int pos = n_g - b * HW;
            *(float4*)&Bs[k][n4] =
                *(const float4*)&x[(size_t)(b * C + kt * 16 + k) * HW + pos];
        }
        __syncthreads();

#pragma unroll
        for (int k = 0; k < 16; k++) {
            float4 a  = *(const float4*)&As[k][ty * 4];
            float4 b0 = *(const float4*)&Bs[k][tx * 8];
            float4 b1 = *(const float4*)&Bs[k][tx * 8 + 4];
            float av[4] = {a.x, a.y, a.z, a.w};
            float bv[8] = {b0.x, b0.y, b0.z, b0.w, b1.x, b1.y, b1.z, b1.w};
#pragma unroll
            for (int im = 0; im < 4; im++)
#pragma unroll
                for (int in = 0; in < 8; in++)
                    acc[im][in] += av[im] * bv[in];
        }
        __syncthreads();
    }

    // epilogue
#pragma unroll
    for (int im = 0; im < 4; im++) {
        int m = m_base + ty * 4 + im;
        if (m >= M_TOT) continue;
        float bia = g_bias[s * M_PAD + m];
#pragma unroll
        for (int in = 0; in < 8; in++) {
            int n_g = n_base + tx * 8 + in;
            int b   = n_g / HW;
            int pos = n_g - b * HW;
            g_out195[((size_t)b * M_TOT + m) * A_TOT + scale_off + pos] = acc[im][in] + bia;
        }
    }
}

// ---------------------------------------------------------------------------
// Per-anchor decode: DFL softmax -> dbox, class max/argmax -> score, kpts.
// One thread per (b, anchor); loads coalesced across anchors.
// ---------------------------------------------------------------------------
__global__ void __launch_bounds__(256) stage2_k()
{
    int idx = blockIdx.x * blockDim.x + threadIdx.x;
    if (idx >= BS * A_TOT) return;
    int b = idx / A_TOT;
    int a = idx - b * A_TOT;

    int W, pos; float stride;
    if (a < 6400)      { W = 80; stride = 8.f;  pos = a; }
    else if (a < 8000) { W = 40; stride = 16.f; pos = a - 6400; }
    else               { W = 20; stride = 32.f; pos = a - 8000; }
    int py = pos / W;
    int px = pos - py * W;
    float gx = px + 0.5f, gy = py + 0.5f;

    const float* base = g_out195 + (size_t)b * M_TOT * A_TOT + a;

    // DFL: softmax over 16 bins per side, expectation with bin index
    float dist[4];
#pragma unroll
    for (int f = 0; f < 4; f++) {
        float v[REGM];
        float mx = -INFINITY;
#pragma unroll
        for (int r = 0; r < REGM; r++) {
            v[r] = base[(size_t)(f * REGM + r) * A_TOT];
            mx = fmaxf(mx, v[r]);
        }
        float sum = 0.f, ws = 0.f;
#pragma unroll
        for (int r = 0; r < REGM; r++) {
            float e = expf(v[r] - mx);
            sum += e;
            ws  += e * (float)r;
        }
        dist[f] = ws / sum;
    }
    float x1 = gx - dist[0], y1 = gy - dist[1];
    float x2 = gx + dist[2], y2 = gy + dist[3];
    g_dbox[((size_t)b * 4 + 0) * A_TOT + a] = (x1 + x2) * 0.5f * stride;
    g_dbox[((size_t)b * 4 + 1) * A_TOT + a] = (y1 + y2) * 0.5f * stride;
    g_dbox[((size_t)b * 4 + 2) * A_TOT + a] = (x2 - x1) * stride;
    g_dbox[((size_t)b * 4 + 3) * A_TOT + a] = (y2 - y1) * stride;

    // class scores: sigmoid monotonic -> argmax/max over logits
    float best = -INFINITY; int bid = 0;
    for (int c = 0; c < NCLS; c++) {
        float v = base[(size_t)(64 + c) * A_TOT];
        if (v > best) { best = v; bid = c; }
    }
    g_maxs[b * A_TOT + a] = 1.f / (1.f + expf(-best));
    g_cls[b * A_TOT + a]  = bid;

    // keypoints: nk = kp*3 + comp
#pragma unroll
    for (int nk = 0; nk < NKPT; nk++) {
        float v = base[(size_t)(144 + nk) * A_TOT];
        int comp = nk % 3;
        float o;
        if (comp == 0)      o = (v * 2.f + (gx - 0.5f)) * stride;
        else if (comp == 1) o = (v * 2.f + (gy - 0.5f)) * stride;
        else                o = 1.f / (1.f + expf(-v));
        g_kpts[((size_t)b * NKPT + nk) * A_TOT + a] = o;
    }
}

// ---------------------------------------------------------------------------
// Per-batch stable top-100 (value desc, index asc on ties = lax.top_k) +
// fused gather into output.
// ---------------------------------------------------------------------------
__global__ void __launch_bounds__(256) topk_k(float* __restrict__ out)
{
    __shared__ float sv[A_TOT];
    __shared__ float rv[256];
    __shared__ int   ri[256];
    __shared__ int   s_idx[MAX_DET];
    __shared__ float s_val[MAX_DET];

    int b = blockIdx.x;
    int t = threadIdx.x;

    for (int i = t; i < A_TOT; i += 256) sv[i] = g_maxs[b * A_TOT + i];
    __syncthreads();

    for (int j = 0; j < MAX_DET; j++) {
        float bv = -INFINITY; int bi = 0x7fffffff;
        for (int i = t; i < A_TOT; i += 256) {
            float v = sv[i];
            if (v > bv) { bv = v; bi = i; }   // i ascending -> first index on tie
        }
        rv[t] = bv; ri[t] = bi;
        __syncthreads();
        for (int o = 128; o > 0; o >>= 1) {
            if (t < o) {
                float v2 = rv[t + o]; int i2 = ri[t + o];
                if (v2 > rv[t] || (v2 == rv[t] && i2 < ri[t])) { rv[t] = v2; ri[t] = i2; }
            }
            __syncthreads();
        }
        if (t == 0) {
            s_idx[j] = ri[0];
            s_val[j] = rv[0];
            sv[ri[0]] = -INFINITY;
        }
        __syncthreads();
    }

    // gather outputs
    if (t == 0) {
        int cnt = 0;
        for (int j = 0; j < MAX_DET; j++) cnt += (s_val[j] > CONF) ? 1 : 0;
        out[O_NUM + b] = (float)cnt;
    }
    for (int e = t; e < MAX_DET * 4; e += 256) {
        int j = e >> 2, c = e & 3;
        out[O_BOX + ((size_t)b * MAX_DET + j) * 4 + c] =
            g_dbox[((size_t)b * 4 + c) * A_TOT + s_idx[j]];
    }
    for (int j = t; j < MAX_DET; j += 256) {
        out[O_SCORE + b * MAX_DET + j] = s_val[j];
        out[O_CLS   + b * MAX_DET + j] = (float)g_cls[b * A_TOT + s_idx[j]];
    }
    for (int e = t; e < MAX_DET * NKPT; e += 256) {
        int j = e / NKPT, nk = e - j * NKPT;
        out[O_KPT + ((size_t)b * MAX_DET + j) * NKPT + nk] =
            g_kpts[((size_t)b * NKPT + nk) * A_TOT + s_idx[j]];
    }
}

// ---------------------------------------------------------------------------
extern "C" void kernel_launch(void* const* d_in, const int* in_sizes, int n_in,
                              void* d_out, int out_size)
{
    const float* xs[3]   = {(const float*)d_in[0], (const float*)d_in[1], (const float*)d_in[2]};
    const float* cv2w[3] = {(const float*)d_in[3], (const float*)d_in[5], (const float*)d_in[7]};
    const float* cv2b[3] = {(const float*)d_in[4], (const float*)d_in[6], (const float*)d_in[8]};
    const float* cv3w[3] = {(const float*)d_in[9], (const float*)d_in[11], (const float*)d_in[13]};
    const float* cv3b[3] = {(const float*)d_in[10], (const float*)d_in[12], (const float*)d_in[14]};
    const float* cv4w[3] = {(const float*)d_in[15], (const float*)d_in[17], (const float*)d_in[19]};
    const float* cv4b[3] = {(const float*)d_in[16], (const float*)d_in[18], (const float*)d_in[20]};

    const int Cs[3]   = {128, 256, 512};
    const int HWs[3]  = {6400, 1600, 400};
    const int kro[3]  = {0, 128, 384};
    const int soff[3] = {0, 6400, 8000};
    const int nblk[3] = {800, 200, 50};   // 16*HW / 128

    for (int s = 0; s < 3; s++)
        pack_k<<<Cs[s], 256>>>(cv2w[s], cv2b[s], cv3w[s], cv3b[s], cv4w[s], cv4b[s],
                               Cs[s], kro[s], s);
    for (int s = 0; s < 3; s++)
        gemm_k<<<dim3(nblk[s], 4), 256>>>(xs[s], Cs[s], HWs[s], kro[s], soff[s], s);

    stage2_k<<<(BS * A_TOT + 255) / 256, 256>>>();
    topk_k<<<BS, 256>>>((float*)d_out);
}

// round 2
// speedup vs baseline: 1.4730x; 1.4730x over previous
#include <cuda_runtime.h>
#include <math.h>

#define BS 16
#define NCLS 80
#define REGM 16
#define NKPT 51
#define A_TOT 8400
#define MAX_DET 100
#define M_TOT 195
#define M_PAD 256
#define CONF 0.25f

// output layout (floats)
#define O_NUM   0
#define O_BOX   16
#define O_SCORE 6416
#define O_CLS   8016
#define O_KPT   9616

// scratch (device globals — no allocation allowed)
__device__ float g_wt[(128 + 256 + 512) * M_PAD];   // k-major packed weights, padded M=256
__device__ float g_bias[3 * M_PAD];
__device__ float g_out195[(size_t)BS * M_TOT * A_TOT];   // [b][m][a]
__device__ float g_dbox[(size_t)BS * 4 * A_TOT];
__device__ float g_kpts[(size_t)BS * NKPT * A_TOT];
__device__ float g_maxs[BS * A_TOT];
__device__ int   g_cls[BS * A_TOT];

// ---------------------------------------------------------------------------
__global__ void pack_k(const float* __restrict__ w2, const float* __restrict__ b2,
                       const float* __restrict__ w3, const float* __restrict__ b3,
                       const float* __restrict__ w4, const float* __restrict__ b4,
                       int C, int krow_off, int s)
{
    int idx = blockIdx.x * blockDim.x + threadIdx.x;
    if (idx >= C * M_PAD) return;
    int k = idx / M_PAD;
    int m = idx - k * M_PAD;
    float v = 0.f;
    if (m < 64)        v = w2[m * C + k];
    else if (m < 144)  v = w3[(m - 64) * C + k];
    else if (m < 195)  v = w4[(m - 144) * C + k];
    g_wt[(size_t)(krow_off + k) * M_PAD + m] = v;
    if (k == 0) {
        float bb = 0.f;
        if (m < 64)        bb = b2[m];
        else if (m < 144)  bb = b3[m - 64];
        else if (m < 195)  bb = b4[m - 144];
        g_bias[s * M_PAD + m] = bb;
    }
}

// ---------------------------------------------------------------------------
// SGEMM 128x128x8, 256 threads, 8x8 register tile, double-buffered smem,
// global loads prefetched into registers across the sync.
// out195[b][m][scale_off+pos] = sum_k W[m][k]*x[b][k][pos] + bias
// ---------------------------------------------------------------------------
__global__ void __launch_bounds__(256, 2) gemm_k(const float* __restrict__ x,
                                                 int C, int HW,
                                                 int krow_off, int scale_off, int s)
{
    __shared__ float As[2][8][128];
    __shared__ float Bs[2][8][128];

    const int tid = threadIdx.x;
    const int tx = tid & 15;            // N dir (8 cols each)
    const int ty = tid >> 4;            // M dir (8 rows each)
    const int m_base = blockIdx.y * 128;
    const int n_base = blockIdx.x * 128;

    // loader mapping: one float4 per thread per tile
    const int lk  = tid >> 5;           // 0..7 (k row)
    const int lm4 = (tid & 31) << 2;    // 0..124

    // B column for this thread's load (HW % 4 == 0 -> float4 stays in batch)
    const int n_g = n_base + lm4;
    const int bb  = n_g / HW;
    const int pos = n_g - bb * HW;
    const float* xb = x + (size_t)bb * C * HW + pos;
    const float* wb = g_wt + (size_t)(krow_off + lk) * M_PAD + m_base + lm4;

    float4 a_reg = *(const float4*)wb;
    float4 b_reg = *(const float4*)&xb[(size_t)lk * HW];
    *(float4*)&As[0][lk][lm4] = a_reg;
    *(float4*)&Bs[0][lk][lm4] = b_reg;
    __syncthreads();

    float acc[8][8];
#pragma unroll
    for (int i = 0; i < 8; i++)
#pragma unroll
        for (int j = 0; j < 8; j++) acc[i][j] = 0.f;

    const int nKt = C >> 3;
    for (int kt = 0; kt < nKt; ++kt) {
        const int buf = kt & 1;
        if (kt + 1 < nKt) {
            a_reg = *(const float4*)&wb[(size_t)(kt + 1) * 8 * M_PAD];
            b_reg = *(const float4*)&xb[(size_t)((kt + 1) * 8 + lk) * HW];
        }
#pragma unroll
        for (int kk = 0; kk < 8; ++kk) {
            float4 a0 = *(const float4*)&As[buf][kk][ty * 8];
            float4 a1 = *(const float4*)&As[buf][kk][ty * 8 + 4];
            float4 b0 = *(const float4*)&Bs[buf][kk][tx * 8];
            float4 b1 = *(const float4*)&Bs[buf][kk][tx * 8 + 4];
            float av[8] = {a0.x, a0.y, a0.z, a0.w, a1.x, a1.y, a1.z, a1.w};
            float bv[8] = {b0.x, b0.y, b0.z, b0.w, b1.x, b1.y, b1.z, b1.w};
#pragma unroll
            for (int im = 0; im < 8; im++)
#pragma unroll
                for (int in = 0; in < 8; in++)
                    acc[im][in] += av[im] * bv[in];
        }
        if (kt + 1 < nKt) {
            *(float4*)&As[buf ^ 1][lk][lm4] = a_reg;
            *(float4*)&Bs[buf ^ 1][lk][lm4] = b_reg;
        }
        __syncthreads();
    }

    // epilogue: n frag (8 wide, 8-aligned) never straddles a batch (HW%8==0)
    const int n_g0 = n_base + tx * 8;
    const int ob   = n_g0 / HW;
    const int opos = n_g0 - ob * HW;
#pragma unroll
    for (int im = 0; im < 8; im++) {
        const int m = m_base + ty * 8 + im;
        if (m >= M_TOT) continue;
        const float bia = g_bias[s * M_PAD + m];
        float4 r0, r1;
        r0.x = acc[im][0] + bia; r0.y = acc[im][1] + bia;
        r0.z = acc[im][2] + bia; r0.w = acc[im][3] + bia;
        r1.x = acc[im][4] + bia; r1.y = acc[im][5] + bia;
        r1.z = acc[im][6] + bia; r1.w = acc[im][7] + bia;
        float* o = &g_out195[((size_t)ob * M_TOT + m) * A_TOT + scale_off + opos];
        *(float4*)o       = r0;
        *(float4*)(o + 4) = r1;
    }
}

// ---------------------------------------------------------------------------
// Per-anchor decode: DFL softmax -> dbox, class max/argmax -> score, kpts.
// ---------------------------------------------------------------------------
__global__ void __launch_bounds__(256) stage2_k()
{
    int idx = blockIdx.x * blockDim.x + threadIdx.x;
    if (idx >= BS * A_TOT) return;
    int b = idx / A_TOT;
    int a = idx - b * A_TOT;

    int W, pos; float stride;
    if (a < 6400)      { W = 80; stride = 8.f;  pos = a; }
    else if (a < 8000) { W = 40; stride = 16.f; pos = a - 6400; }
    else               { W = 20; stride = 32.f; pos = a - 8000; }
    int py = pos / W;
    int px = pos - py * W;
    float gx = px + 0.5f, gy = py + 0.5f;

    const float* base = g_out195 + (size_t)b * M_TOT * A_TOT + a;

    float dist[4];
#pragma unroll
    for (int f = 0; f < 4; f++) {
        float v[REGM];
        float mx = -INFINITY;
#pragma unroll
        for (int r = 0; r < REGM; r++) {
            v[r] = base[(size_t)(f * REGM + r) * A_TOT];
            mx = fmaxf(mx, v[r]);
        }
        float sum = 0.f, ws = 0.f;
#pragma unroll
        for (int r = 0; r < REGM; r++) {
            float e = expf(v[r] - mx);
            sum += e;
            ws  += e * (float)r;
        }
        dist[f] = ws / sum;
    }
    float x1 = gx - dist[0], y1 = gy - dist[1];
    float x2 = gx + dist[2], y2 = gy + dist[3];
    g_dbox[((size_t)b * 4 + 0) * A_TOT + a] = (x1 + x2) * 0.5f * stride;
    g_dbox[((size_t)b * 4 + 1) * A_TOT + a] = (y1 + y2) * 0.5f * stride;
    g_dbox[((size_t)b * 4 + 2) * A_TOT + a] = (x2 - x1) * stride;
    g_dbox[((size_t)b * 4 + 3) * A_TOT + a] = (y2 - y1) * stride;

    float best = -INFINITY; int bid = 0;
    for (int c = 0; c < NCLS; c++) {
        float v = base[(size_t)(64 + c) * A_TOT];
        if (v > best) { best = v; bid = c; }
    }
    g_maxs[b * A_TOT + a] = 1.f / (1.f + expf(-best));
    g_cls[b * A_TOT + a]  = bid;

#pragma unroll
    for (int nk = 0; nk < NKPT; nk++) {
        float v = base[(size_t)(144 + nk) * A_TOT];
        int comp = nk % 3;
        float o;
        if (comp == 0)      o = (v * 2.f + (gx - 0.5f)) * stride;
        else if (comp == 1) o = (v * 2.f + (gy - 0.5f)) * stride;
        else                o = 1.f / (1.f + expf(-v));
        g_kpts[((size_t)b * NKPT + nk) * A_TOT + a] = o;
    }
}

// ---------------------------------------------------------------------------
// Per-batch stable top-100 (value desc, index asc on ties) — 1024 threads,
// warp-shuffle reductions; fused gather into output.
// ---------------------------------------------------------------------------
__global__ void __launch_bounds__(1024) topk_k(float* __restrict__ out)
{
    __shared__ float sv[A_TOT];
    __shared__ float wv[32];
    __shared__ int   wi[32];
    __shared__ int   s_idx[MAX_DET];
    __shared__ float s_val[MAX_DET];

    const int b = blockIdx.x;
    const int t = threadIdx.x;
    const int lane = t & 31;
    const int warp = t >> 5;

    for (int i = t; i < A_TOT; i += 1024) sv[i] = g_maxs[b * A_TOT + i];
    __syncthreads();

    for (int j = 0; j < MAX_DET; j++) {
        float bv = -INFINITY; int bi = 0x7fffffff;
        for (int i = t; i < A_TOT; i += 1024) {
            float v = sv[i];
            if (v > bv) { bv = v; bi = i; }     // ascending i -> first index on tie
        }
#pragma unroll
        for (int o = 16; o; o >>= 1) {
            float v2 = __shfl_down_sync(0xffffffffu, bv, o);
            int   i2 = __shfl_down_sync(0xffffffffu, bi, o);
            if (v2 > bv || (v2 == bv && i2 < bi)) { bv = v2; bi = i2; }
        }
        if (lane == 0) { wv[warp] = bv; wi[warp] = bi; }
        __syncthreads();
        if (warp == 0) {
            bv = wv[lane]; bi = wi[lane];
#pragma unroll
            for (int o = 16; o; o >>= 1) {
                float v2 = __shfl_down_sync(0xffffffffu, bv, o);
                int   i2 = __shfl_down_sync(0xffffffffu, bi, o);
                if (v2 > bv || (v2 == bv && i2 < bi)) { bv = v2; bi = i2; }
            }
            if (lane == 0) {
                s_idx[j] = bi;
                s_val[j] = bv;
                sv[bi] = -INFINITY;
            }
        }
        __syncthreads();
    }

    if (t == 0) {
        int cnt = 0;
        for (int j = 0; j < MAX_DET; j++) cnt += (s_val[j] > CONF) ? 1 : 0;
        out[O_NUM + b] = (float)cnt;
    }
    for (int e = t; e < MAX_DET * 4; e += 1024) {
        int j = e >> 2, c = e & 3;
        out[O_BOX + ((size_t)b * MAX_DET + j) * 4 + c] =
            g_dbox[((size_t)b * 4 + c) * A_TOT + s_idx[j]];
    }
    for (int j = t; j < MAX_DET; j += 1024) {
        out[O_SCORE + b * MAX_DET + j] = s_val[j];
        out[O_CLS   + b * MAX_DET + j] = (float)g_cls[b * A_TOT + s_idx[j]];
    }
    for (int e = t; e < MAX_DET * NKPT; e += 1024) {
        int j = e / NKPT, nk = e - j * NKPT;
        out[O_KPT + ((size_t)b * MAX_DET + j) * NKPT + nk] =
            g_kpts[((size_t)b * NKPT + nk) * A_TOT + s_idx[j]];
    }
}

// ---------------------------------------------------------------------------
extern "C" void kernel_launch(void* const* d_in, const int* in_sizes, int n_in,
                              void* d_out, int out_size)
{
    const float* xs[3]   = {(const float*)d_in[0], (const float*)d_in[1], (const float*)d_in[2]};
    const float* cv2w[3] = {(const float*)d_in[3], (const float*)d_in[5], (const float*)d_in[7]};
    const float* cv2b[3] = {(const float*)d_in[4], (const float*)d_in[6], (const float*)d_in[8]};
    const float* cv3w[3] = {(const float*)d_in[9], (const float*)d_in[11], (const float*)d_in[13]};
    const float* cv3b[3] = {(const float*)d_in[10], (const float*)d_in[12], (const float*)d_in[14]};
    const float* cv4w[3] = {(const float*)d_in[15], (const float*)d_in[17], (const float*)d_in[19]};
    const float* cv4b[3] = {(const float*)d_in[16], (const float*)d_in[18], (const float*)d_in[20]};

    const int Cs[3]   = {128, 256, 512};
    const int HWs[3]  = {6400, 1600, 400};
    const int kro[3]  = {0, 128, 384};
    const int soff[3] = {0, 6400, 8000};
    const int nblk[3] = {800, 200, 50};   // 16*HW / 128

    for (int s = 0; s < 3; s++)
        pack_k<<<Cs[s], 256>>>(cv2w[s], cv2b[s], cv3w[s], cv3b[s], cv4w[s], cv4b[s],
                               Cs[s], kro[s], s);
    for (int s = 0; s < 3; s++)
        gemm_k<<<dim3(nblk[s], 2), 256>>>(xs[s], Cs[s], HWs[s], kro[s], soff[s], s);

    stage2_k<<<(BS * A_TOT + 255) / 256, 256>>>();
    topk_k<<<BS, 1024>>>((float*)d_out);
}

// round 4
// speedup vs baseline: 2.2410x; 1.5214x over previous
#include <cuda_runtime.h>
#include <cuda_fp16.h>
#include <math.h>
#include <stdint.h>

#define BS 16
#define NCLS 80
#define NKPT 51
#define A_TOT 8400
#define MAX_DET 100
#define CONF 0.25f

// output layout (floats)
#define O_NUM   0
#define O_BOX   16
#define O_SCORE 6416
#define O_CLS   8016
#define O_KPT   9616

// device scratch
__device__ __align__(16) __half g_wh[229376];   // [s][n=256][k] halves, hi part
__device__ __align__(16) __half g_wl[229376];   // lo part
__device__ float g_bias[3 * 256];
__device__ float g_dbox[(size_t)BS * 4 * A_TOT];
__device__ float g_kpts[(size_t)BS * NKPT * A_TOT];
__device__ float g_maxs[BS * A_TOT];
__device__ int   g_cls[BS * A_TOT];

// ---------------------------------------------------------------------------
// Pack: split weights into fp16 hi/lo, [n][k] layout (k contiguous), + bias.
// ---------------------------------------------------------------------------
__global__ void pack_k(const float* __restrict__ w2, const float* __restrict__ b2,
                       const float* __restrict__ w3, const float* __restrict__ b3,
                       const float* __restrict__ w4, const float* __restrict__ b4,
                       int C, int woff, int s)
{
    int idx = blockIdx.x * blockDim.x + threadIdx.x;
    if (idx >= 256 * C) return;
    int n = idx / C;
    int k = idx - n * C;
    float v = 0.f;
    if (n < 64)        v = w2[n * C + k];
    else if (n < 144)  v = w3[(n - 64) * C + k];
    else if (n < 195)  v = w4[(n - 144) * C + k];
    __half h = __float2half_rn(v);
    g_wh[woff + idx] = h;
    g_wl[woff + idx] = __float2half_rn(v - __half2float(h));
    if (k == 0) {
        float bb = 0.f;
        if (n < 64)        bb = b2[n];
        else if (n < 144)  bb = b3[n - 64];
        else if (n < 195)  bb = b4[n - 144];
        g_bias[s * 256 + n] = bb;
    }
}

// ---------------------------------------------------------------------------
__device__ __forceinline__ void mma_f16(float* c, const uint32_t* a,
                                        uint32_t b0, uint32_t b1)
{
    asm volatile(
        "mma.sync.aligned.m16n8k16.row.col.f32.f16.f16.f32 "
        "{%0,%1,%2,%3}, {%4,%5,%6,%7}, {%8,%9}, {%0,%1,%2,%3};"
        : "+f"(c[0]), "+f"(c[1]), "+f"(c[2]), "+f"(c[3])
        : "r"(a[0]), "r"(a[1]), "r"(a[2]), "r"(a[3]), "r"(b0), "r"(b1));
}

__device__ __forceinline__ float dfl16(const float* v) {
    float mx = v[0];
#pragma unroll
    for (int i = 1; i < 16; i++) mx = fmaxf(mx, v[i]);
    float s = 0.f, w = 0.f;
#pragma unroll
    for (int i = 0; i < 16; i++) {
        float e = expf(v[i] - mx);
        s += e;
        w += e * (float)i;
    }
    return w / s;
}

// smem word offsets
#define SM_AH   0                    // 16 kpairs x 136 words (half2 per word)
#define SM_AL   2176
#define SM_BH   4352                 // 256 n x 20 words
#define SM_BL   9472
#define SM_D    14592                // 128 m x 201 words (fp32)
#define SM_BIAS 40320                // 256 fp32
#define SM_WORDS 40576
#define SMEM_BYTES (SM_WORDS * 4)    // 162304

// ---------------------------------------------------------------------------
// Fused GEMM (split-fp16 mma.sync) + decode epilogue. One launch, 1072 CTAs.
// D[128 anchors][256 outs] = X[128 pos][K ch] * W[256 outs][K ch]^T (+bias in
// decode). 512 threads = 16 warps, warp tile 32(M) x 64(N), K-chunk 32.
// ---------------------------------------------------------------------------
__global__ void __launch_bounds__(512, 1) gemm_tc(const float* __restrict__ x0,
                                                  const float* __restrict__ x1,
                                                  const float* __restrict__ x2)
{
    extern __shared__ uint32_t sm[];
    float* smf = (float*)sm;

    // ---- scale / batch / tile from flat block index ----
    int bid = blockIdx.x;
    int s, rel;
    if (bid < 800)       { s = 0; rel = bid; }
    else if (bid < 1008) { s = 1; rel = bid - 800; }
    else                 { s = 2; rel = bid - 1008; }
    const int tpbA[3]  = {50, 13, 4};
    const int CsA[3]   = {128, 256, 512};
    const int HWA[3]   = {6400, 1600, 400};
    const int soffA[3] = {0, 6400, 8000};
    const int WA[3]    = {80, 40, 20};
    const int woffA[3] = {0, 32768, 98304};
    const float strA[3] = {8.f, 16.f, 32.f};

    const int C = CsA[s], HW = HWA[s], W = WA[s];
    const float stride = strA[s];
    const int b    = rel / tpbA[s];
    const int tile = rel - b * tpbA[s];
    const int pos0 = tile * 128;
    const int valid = min(128, HW - pos0);

    const float* xsel = (s == 0) ? x0 : (s == 1) ? x1 : x2;
    const float* xb = xsel + (size_t)b * C * HW + pos0;
    const __half* wh = g_wh + woffA[s];
    const __half* wl = g_wl + woffA[s];

    const int t = threadIdx.x;
    const int lane = t & 31;
    const int wid = t >> 5;
    const int wm = wid & 3;          // M warp (32 rows)
    const int wn = wid >> 2;         // N warp (64 cols)

    for (int i = t; i < 256; i += 512) smf[SM_BIAS + i] = g_bias[s * 256 + i];

    float acc[16][4];
#pragma unroll
    for (int i = 0; i < 16; i++)
#pragma unroll
        for (int j = 0; j < 4; j++) acc[i][j] = 0.f;

    const int am = t & 127;          // loader m
    const int akp0 = t >> 7;         // loader kpair base 0..3

    const int nkt = C >> 5;
    for (int kt = 0; kt < nkt; kt++) {
        const int c0 = kt << 5;
        // ---- A tile: transpose + hi/lo split. P[kp][m] = half2(ch 2kp, 2kp+1)
#pragma unroll
        for (int p = 0; p < 4; p++) {
            const int kp = akp0 + p * 4;
            float v0 = 0.f, v1 = 0.f;
            if (am < valid) {
                v0 = xb[(size_t)(c0 + 2 * kp) * HW + am];
                v1 = xb[(size_t)(c0 + 2 * kp + 1) * HW + am];
            }
            __half h0 = __float2half_rn(v0);
            __half h1 = __float2half_rn(v1);
            __half l0 = __float2half_rn(v0 - __half2float(h0));
            __half l1 = __float2half_rn(v1 - __half2float(h1));
            __half2 hh = __halves2half2(h0, h1);
            __half2 ll = __halves2half2(l0, l1);
            sm[SM_AH + kp * 136 + am] = *(uint32_t*)&hh;
            sm[SM_AL + kp * 136 + am] = *(uint32_t*)&ll;
        }
        // ---- B tile: copy pre-split fp16 weights, rows of 32 halves ----
#pragma unroll
        for (int i = 0; i < 2; i++) {
            const int idx = t + i * 512;
            const int n = idx >> 2;
            const int off = idx & 3;
            const uint4 vh = *(const uint4*)(wh + (size_t)n * C + c0 + off * 8);
            const uint4 vl = *(const uint4*)(wl + (size_t)n * C + c0 + off * 8);
            *(uint4*)&sm[SM_BH + n * 20 + off * 4] = vh;
            *(uint4*)&sm[SM_BL + n * 20 + off * 4] = vl;
        }
        __syncthreads();

        // ---- compute: 2 k16 steps ----
#pragma unroll
        for (int k16 = 0; k16 < 2; k16++) {
            uint32_t ah[2][4], al[2][4];
#pragma unroll
            for (int mt = 0; mt < 2; mt++) {
                const int mb = wm * 32 + mt * 16 + (lane >> 2);
                const int kp = (lane & 3) + k16 * 8;
                ah[mt][0] = sm[SM_AH + kp * 136 + mb];
                ah[mt][1] = sm[SM_AH + kp * 136 + mb + 8];
                ah[mt][2] = sm[SM_AH + (kp + 4) * 136 + mb];
                ah[mt][3] = sm[SM_AH + (kp + 4) * 136 + mb + 8];
                al[mt][0] = sm[SM_AL + kp * 136 + mb];
                al[mt][1] = sm[SM_AL + kp * 136 + mb + 8];
                al[mt][2] = sm[SM_AL + (kp + 4) * 136 + mb];
                al[mt][3] = sm[SM_AL + (kp + 4) * 136 + mb + 8];
            }
#pragma unroll
            for (int nt = 0; nt < 8; nt++) {
                const int n = wn * 64 + nt * 8 + (lane >> 2);
                const int kw = (lane & 3) + k16 * 8;
                const uint32_t bh0 = sm[SM_BH + n * 20 + kw];
                const uint32_t bh1 = sm[SM_BH + n * 20 + kw + 4];
                const uint32_t bl0 = sm[SM_BL + n * 20 + kw];
                const uint32_t bl1 = sm[SM_BL + n * 20 + kw + 4];
#pragma unroll
                for (int mt = 0; mt < 2; mt++) {
                    float* c = acc[nt * 2 + mt];
                    mma_f16(c, ah[mt], bh0, bh1);   // hi*hi
                    mma_f16(c, ah[mt], bl0, bl1);   // hi*lo
                    mma_f16(c, al[mt], bh0, bh1);   // lo*hi
                }
            }
        }
        __syncthreads();
    }

    // ---- stage D tile (cols 0..199 kept, stride 201) ----
#pragma unroll
    for (int nt = 0; nt < 8; nt++) {
        const int n = wn * 64 + nt * 8 + (lane & 3) * 2;
        if (n >= 200) continue;
#pragma unroll
        for (int mt = 0; mt < 2; mt++) {
            const int r = wm * 32 + mt * 16 + (lane >> 2);
            const float* c = acc[nt * 2 + mt];
            smf[SM_D + r * 201 + n]           = c[0];
            smf[SM_D + r * 201 + n + 1]       = c[1];
            smf[SM_D + (r + 8) * 201 + n]     = c[2];
            smf[SM_D + (r + 8) * 201 + n + 1] = c[3];
        }
    }
    __syncthreads();

    // ---- decode epilogue: thread t<128 owns anchor row t ----
    if (t < 128) {
        const bool ok = t < valid;
        const int pos = pos0 + t;
        const int a_g = soffA[s] + pos;
        const int py = pos / W, px = pos - py * W;
        const float gx = px + 0.5f, gy = py + 0.5f;
        const float* Dr = smf + SM_D + t * 201;
        const float* bi = smf + SM_BIAS;

        float dist[4], v16[16];
#pragma unroll
        for (int f = 0; f < 4; f++) {
#pragma unroll
            for (int i = 0; i < 16; i++) v16[i] = Dr[f * 16 + i] + bi[f * 16 + i];
            dist[f] = dfl16(v16);
        }
        if (ok) {
            float x1 = gx - dist[0], y1 = gy - dist[1];
            float x2 = gx + dist[2], y2 = gy + dist[3];
            g_dbox[((size_t)b * 4 + 0) * A_TOT + a_g] = (x1 + x2) * 0.5f * stride;
            g_dbox[((size_t)b * 4 + 1) * A_TOT + a_g] = (y1 + y2) * 0.5f * stride;
            g_dbox[((size_t)b * 4 + 2) * A_TOT + a_g] = (x2 - x1) * stride;
            g_dbox[((size_t)b * 4 + 3) * A_TOT + a_g] = (y2 - y1) * stride;
        }

        float best = -INFINITY; int bcls = 0;
#pragma unroll
        for (int c = 0; c < NCLS; c++) {
            float v = Dr[64 + c] + bi[64 + c];
            if (v > best) { best = v; bcls = c; }
        }
        if (ok) {
            g_maxs[b * A_TOT + a_g] = 1.f / (1.f + expf(-best));
            g_cls[b * A_TOT + a_g]  = bcls;
        }

        if (ok) {
#pragma unroll
            for (int nk = 0; nk < NKPT; nk++) {
                float v = Dr[144 + nk] + bi[144 + nk];
                const int comp = nk % 3;
                float o = (comp == 0) ? (v * 2.f + (gx - 0.5f)) * stride
                        : (comp == 1) ? (v * 2.f + (gy - 0.5f)) * stride
                                      : 1.f / (1.f + expf(-v));
                g_kpts[((size_t)b * NKPT + nk) * A_TOT + a_g] = o;
            }
        }
    }
}

// ---------------------------------------------------------------------------
// Per-batch stable top-100 + gather (unchanged).
// ---------------------------------------------------------------------------
__global__ void __launch_bounds__(1024) topk_k(float* __restrict__ out)
{
    __shared__ float sv[A_TOT];
    __shared__ float wv[32];
    __shared__ int   wi[32];
    __shared__ int   s_idx[MAX_DET];
    __shared__ float s_val[MAX_DET];

    const int b = blockIdx.x;
    const int t = threadIdx.x;
    const int lane = t & 31;
    const int warp = t >> 5;

    for (int i = t; i < A_TOT; i += 1024) sv[i] = g_maxs[b * A_TOT + i];
    __syncthreads();

    for (int j = 0; j < MAX_DET; j++) {
        float bv = -INFINITY; int bi = 0x7fffffff;
        for (int i = t; i < A_TOT; i += 1024) {
            float v = sv[i];
            if (v > bv) { bv = v; bi = i; }
        }
#pragma unroll
        for (int o = 16; o; o >>= 1) {
            float v2 = __shfl_down_sync(0xffffffffu, bv, o);
            int   i2 = __shfl_down_sync(0xffffffffu, bi, o);
            if (v2 > bv || (v2 == bv && i2 < bi)) { bv = v2; bi = i2; }
        }
        if (lane == 0) { wv[warp] = bv; wi[warp] = bi; }
        __syncthreads();
        if (warp == 0) {
            bv = wv[lane]; bi = wi[lane];
#pragma unroll
            for (int o = 16; o; o >>= 1) {
                float v2 = __shfl_down_sync(0xffffffffu, bv, o);
                int   i2 = __shfl_down_sync(0xffffffffu, bi, o);
                if (v2 > bv || (v2 == bv && i2 < bi)) { bv = v2; bi = i2; }
            }
            if (lane == 0) {
                s_idx[j] = bi;
                s_val[j] = bv;
                sv[bi] = -INFINITY;
            }
        }
        __syncthreads();
    }

    if (t == 0) {
        int cnt = 0;
        for (int j = 0; j < MAX_DET; j++) cnt += (s_val[j] > CONF) ? 1 : 0;
        out[O_NUM + b] = (float)cnt;
    }
    for (int e = t; e < MAX_DET * 4; e += 1024) {
        int j = e >> 2, c = e & 3;
        out[O_BOX + ((size_t)b * MAX_DET + j) * 4 + c] =
            g_dbox[((size_t)b * 4 + c) * A_TOT + s_idx[j]];
    }
    for (int j = t; j < MAX_DET; j += 1024) {
        out[O_SCORE + b * MAX_DET + j] = s_val[j];
        out[O_CLS   + b * MAX_DET + j] = (float)g_cls[b * A_TOT + s_idx[j]];
    }
    for (int e = t; e < MAX_DET * NKPT; e += 1024) {
        int j = e / NKPT, nk = e - j * NKPT;
        out[O_KPT + ((size_t)b * MAX_DET + j) * NKPT + nk] =
            g_kpts[((size_t)b * NKPT + nk) * A_TOT + s_idx[j]];
    }
}

// ---------------------------------------------------------------------------
extern "C" void kernel_launch(void* const* d_in, const int* in_sizes, int n_in,
                              void* d_out, int out_size)
{
    const float* xs[3]   = {(const float*)d_in[0], (const float*)d_in[1], (const float*)d_in[2]};
    const float* cv2w[3] = {(const float*)d_in[3], (const float*)d_in[5], (const float*)d_in[7]};
    const float* cv2b[3] = {(const float*)d_in[4], (const float*)d_in[6], (const float*)d_in[8]};
    const float* cv3w[3] = {(const float*)d_in[9], (const float*)d_in[11], (const float*)d_in[13]};
    const float* cv3b[3] = {(const float*)d_in[10], (const float*)d_in[12], (const float*)d_in[14]};
    const float* cv4w[3] = {(const float*)d_in[15], (const float*)d_in[17], (const float*)d_in[19]};
    const float* cv4b[3] = {(const float*)d_in[16], (const float*)d_in[18], (const float*)d_in[20]};

    const int Cs[3]   = {128, 256, 512};
    const int woff[3] = {0, 32768, 98304};

    static int smem_set = 0;
    if (!smem_set) {
        cudaFuncSetAttribute(gemm_tc, cudaFuncAttributeMaxDynamicSharedMemorySize, SMEM_BYTES);
        smem_set = 1;
    }

    for (int s = 0; s < 3; s++)
        pack_k<<<(256 * Cs[s] + 255) / 256, 256>>>(cv2w[s], cv2b[s], cv3w[s], cv3b[s],
                                                   cv4w[s], cv4b[s], Cs[s], woff[s], s);

    gemm_tc<<<1072, 512, SMEM_BYTES>>>(xs[0], xs[1], xs[2]);

    topk_k<<<BS, 1024>>>((float*)d_out);
}

// round 5
// speedup vs baseline: 3.3484x; 1.4941x over previous
#include <cuda_runtime.h>
#include <cuda_fp16.h>
#include <math.h>
#include <stdint.h>

#define BS 16
#define NCLS 80
#define NKPT 51
#define A_TOT 8400
#define MAX_DET 100
#define CONF 0.25f

// output layout (floats)
#define O_NUM   0
#define O_BOX   16
#define O_SCORE 6416
#define O_CLS   8016
#define O_KPT   9616

// device scratch
__device__ __align__(16) __half g_wh[229376];   // [s][n=256][k], hi part
__device__ __align__(16) __half g_wl[229376];   // lo part
__device__ float g_bias[3 * 256];
__device__ float g_dbox[(size_t)BS * 4 * A_TOT];
__device__ float g_kpts[(size_t)BS * NKPT * A_TOT];
__device__ float g_maxs[BS * A_TOT];
__device__ int   g_cls[BS * A_TOT];

// ---------------------------------------------------------------------------
// Pack (single launch, all 3 scales): split weights into fp16 hi/lo + bias.
// ---------------------------------------------------------------------------
__global__ void pack_k(const float* __restrict__ w20, const float* __restrict__ b20,
                       const float* __restrict__ w21, const float* __restrict__ b21,
                       const float* __restrict__ w22, const float* __restrict__ b22,
                       const float* __restrict__ w30, const float* __restrict__ b30,
                       const float* __restrict__ w31, const float* __restrict__ b31,
                       const float* __restrict__ w32, const float* __restrict__ b32,
                       const float* __restrict__ w40, const float* __restrict__ b40,
                       const float* __restrict__ w41, const float* __restrict__ b41,
                       const float* __restrict__ w42, const float* __restrict__ b42)
{
    int gidx = blockIdx.x * blockDim.x + threadIdx.x;
    if (gidx >= 229376) return;
    int s, idx, C;
    if (gidx < 32768)       { s = 0; idx = gidx;          C = 128; }
    else if (gidx < 98304)  { s = 1; idx = gidx - 32768;  C = 256; }
    else                    { s = 2; idx = gidx - 98304;  C = 512; }
    const float* w2 = (s == 0) ? w20 : (s == 1) ? w21 : w22;
    const float* b2 = (s == 0) ? b20 : (s == 1) ? b21 : b22;
    const float* w3 = (s == 0) ? w30 : (s == 1) ? w31 : w32;
    const float* b3 = (s == 0) ? b30 : (s == 1) ? b31 : b32;
    const float* w4 = (s == 0) ? w40 : (s == 1) ? w41 : w42;
    const float* b4 = (s == 0) ? b40 : (s == 1) ? b41 : b42;

    int n = idx / C;
    int k = idx - n * C;
    float v = 0.f;
    if (n < 64)        v = w2[n * C + k];
    else if (n < 144)  v = w3[(n - 64) * C + k];
    else if (n < 195)  v = w4[(n - 144) * C + k];
    __half h = __float2half_rn(v);
    g_wh[gidx] = h;
    g_wl[gidx] = __float2half_rn(v - __half2float(h));
    if (k == 0) {
        float bb = 0.f;
        if (n < 64)        bb = b2[n];
        else if (n < 144)  bb = b3[n - 64];
        else if (n < 195)  bb = b4[n - 144];
        g_bias[s * 256 + n] = bb;
    }
}

// ---------------------------------------------------------------------------
__device__ __forceinline__ void mma_f16(float* c, const uint32_t* a,
                                        uint32_t b0, uint32_t b1)
{
    asm volatile(
        "mma.sync.aligned.m16n8k16.row.col.f32.f16.f16.f32 "
        "{%0,%1,%2,%3}, {%4,%5,%6,%7}, {%8,%9}, {%0,%1,%2,%3};"
        : "+f"(c[0]), "+f"(c[1]), "+f"(c[2]), "+f"(c[3])
        : "r"(a[0]), "r"(a[1]), "r"(a[2]), "r"(a[3]), "r"(b0), "r"(b1));
}

__device__ __forceinline__ float dfl16(const float* v) {
    float mx = v[0];
#pragma unroll
    for (int i = 1; i < 16; i++) mx = fmaxf(mx, v[i]);
    float s = 0.f, w = 0.f;
#pragma unroll
    for (int i = 0; i < 16; i++) {
        float e = expf(v[i] - mx);
        s += e;
        w += e * (float)i;
    }
    return w / s;
}

// smem word offsets (per stage: AH=0, AL=2176, BH=4352, BL=9472; size 14592)
#define ST_WORDS 14592
#define SM_D     29184                 // 128 m x 201 words fp32
#define SM_BIAS  54912                 // 256 fp32
#define SM_WORDS 55168
#define SMEM_BYTES (SM_WORDS * 4)      // 220672

// ---------------------------------------------------------------------------
// Fused GEMM (split-fp16 mma.sync, 2-stage cp.async pipeline) + decode.
// 512 threads = 16 warps, warp tile 32(M) x 64(N), K-chunk 32.
// ---------------------------------------------------------------------------
__global__ void __launch_bounds__(512, 1) gemm_tc(const float* __restrict__ x0,
                                                  const float* __restrict__ x1,
                                                  const float* __restrict__ x2)
{
    extern __shared__ uint32_t sm[];
    float* smf = (float*)sm;

    int bid = blockIdx.x;
    int s, rel;
    if (bid < 800)       { s = 0; rel = bid; }
    else if (bid < 1008) { s = 1; rel = bid - 800; }
    else                 { s = 2; rel = bid - 1008; }
    const int tpbA[3]  = {50, 13, 4};
    const int CsA[3]   = {128, 256, 512};
    const int HWA[3]   = {6400, 1600, 400};
    const int soffA[3] = {0, 6400, 8000};
    const int WA[3]    = {80, 40, 20};
    const int woffA[3] = {0, 32768, 98304};
    const float strA[3] = {8.f, 16.f, 32.f};

    const int C = CsA[s], HW = HWA[s], W = WA[s];
    const float stride = strA[s];
    const int b    = rel / tpbA[s];
    const int tile = rel - b * tpbA[s];
    const int pos0 = tile * 128;
    const int valid = min(128, HW - pos0);

    const float* xsel = (s == 0) ? x0 : (s == 1) ? x1 : x2;
    const float* xb = xsel + (size_t)b * C * HW + pos0;
    const __half* wh = g_wh + woffA[s];
    const __half* wl = g_wl + woffA[s];

    const int t = threadIdx.x;
    const int lane = t & 31;
    const int wid = t >> 5;
    const int wm = wid & 3;
    const int wn = wid >> 2;

    const uint32_t smb = (uint32_t)__cvta_generic_to_shared(sm);

    for (int i = t; i < 256; i += 512) smf[SM_BIAS + i] = g_bias[s * 256 + i];

    float acc[16][4];
#pragma unroll
    for (int i = 0; i < 16; i++)
#pragma unroll
        for (int j = 0; j < 4; j++) acc[i][j] = 0.f;

    const int am = t & 127;
    const int akp0 = t >> 7;
    const int bn = t >> 2;            // B loader row base (with +128)
    const int boff = t & 3;

    const int nkt = C >> 5;

    // ---- prologue: chunk 0 ----
    {
        // B chunk 0 via cp.async (2 rows per thread x hi/lo)
#pragma unroll
        for (int i = 0; i < 2; i++) {
            const int n = bn + i * 128;
            const uint32_t dsth = smb + (4352 + n * 20 + boff * 4) * 4;
            const uint32_t dstl = smb + (9472 + n * 20 + boff * 4) * 4;
            asm volatile("cp.async.cg.shared.global [%0], [%1], 16;"
                         :: "r"(dsth), "l"(wh + (size_t)n * C + boff * 8) : "memory");
            asm volatile("cp.async.cg.shared.global [%0], [%1], 16;"
                         :: "r"(dstl), "l"(wl + (size_t)n * C + boff * 8) : "memory");
        }
        asm volatile("cp.async.commit_group;" ::: "memory");
        // A chunk 0: load + transform + store directly
#pragma unroll
        for (int p = 0; p < 4; p++) {
            const int kp = akp0 + p * 4;
            float v0 = 0.f, v1 = 0.f;
            if (am < valid) {
                v0 = xb[(size_t)(2 * kp) * HW + am];
                v1 = xb[(size_t)(2 * kp + 1) * HW + am];
            }
            __half h0 = __float2half_rn(v0), h1 = __float2half_rn(v1);
            __half l0 = __float2half_rn(v0 - __half2float(h0));
            __half l1 = __float2half_rn(v1 - __half2float(h1));
            __half2 hh = __halves2half2(h0, h1);
            __half2 ll = __halves2half2(l0, l1);
            sm[kp * 136 + am]        = *(uint32_t*)&hh;
            sm[2176 + kp * 136 + am] = *(uint32_t*)&ll;
        }
    }

    for (int kt = 0; kt < nkt; kt++) {
        const int st = (kt & 1) ? ST_WORDS : 0;
        asm volatile("cp.async.wait_group 0;" ::: "memory");
        __syncthreads();

        float apre[8];
        const bool pf = (kt + 1 < nkt);
        const int stn = ((kt + 1) & 1) ? ST_WORDS : 0;
        if (pf) {
            const int c1 = (kt + 1) << 5;
            // B prefetch via cp.async into other stage
#pragma unroll
            for (int i = 0; i < 2; i++) {
                const int n = bn + i * 128;
                const uint32_t dsth = smb + (stn + 4352 + n * 20 + boff * 4) * 4;
                const uint32_t dstl = smb + (stn + 9472 + n * 20 + boff * 4) * 4;
                asm volatile("cp.async.cg.shared.global [%0], [%1], 16;"
                             :: "r"(dsth), "l"(wh + (size_t)n * C + c1 + boff * 8) : "memory");
                asm volatile("cp.async.cg.shared.global [%0], [%1], 16;"
                             :: "r"(dstl), "l"(wl + (size_t)n * C + c1 + boff * 8) : "memory");
            }
            asm volatile("cp.async.commit_group;" ::: "memory");
            // A prefetch into registers
#pragma unroll
            for (int p = 0; p < 4; p++) {
                const int kp = akp0 + p * 4;
                float v0 = 0.f, v1 = 0.f;
                if (am < valid) {
                    v0 = xb[(size_t)(c1 + 2 * kp) * HW + am];
                    v1 = xb[(size_t)(c1 + 2 * kp + 1) * HW + am];
                }
                apre[p * 2]     = v0;
                apre[p * 2 + 1] = v1;
            }
        }

        // ---- compute current chunk ----
#pragma unroll
        for (int k16 = 0; k16 < 2; k16++) {
            uint32_t ah[2][4], al[2][4];
#pragma unroll
            for (int mt = 0; mt < 2; mt++) {
                const int mb = wm * 32 + mt * 16 + (lane >> 2);
                const int kp = (lane & 3) + k16 * 8;
                ah[mt][0] = sm[st + kp * 136 + mb];
                ah[mt][1] = sm[st + kp * 136 + mb + 8];
                ah[mt][2] = sm[st + (kp + 4) * 136 + mb];
                ah[mt][3] = sm[st + (kp + 4) * 136 + mb + 8];
                al[mt][0] = sm[st + 2176 + kp * 136 + mb];
                al[mt][1] = sm[st + 2176 + kp * 136 + mb + 8];
                al[mt][2] = sm[st + 2176 + (kp + 4) * 136 + mb];
                al[mt][3] = sm[st + 2176 + (kp + 4) * 136 + mb + 8];
            }
#pragma unroll
            for (int nt = 0; nt < 8; nt++) {
                const int n = wn * 64 + nt * 8 + (lane >> 2);
                const int kw = (lane & 3) + k16 * 8;
                const uint32_t bh0 = sm[st + 4352 + n * 20 + kw];
                const uint32_t bh1 = sm[st + 4352 + n * 20 + kw + 4];
                const uint32_t bl0 = sm[st + 9472 + n * 20 + kw];
                const uint32_t bl1 = sm[st + 9472 + n * 20 + kw + 4];
#pragma unroll
                for (int mt = 0; mt < 2; mt++) {
                    float* c = acc[nt * 2 + mt];
                    mma_f16(c, ah[mt], bh0, bh1);
                    mma_f16(c, ah[mt], bl0, bl1);
                    mma_f16(c, al[mt], bh0, bh1);
                }
            }
        }

        if (pf) {
            // transform prefetched A into other stage
#pragma unroll
            for (int p = 0; p < 4; p++) {
                const int kp = akp0 + p * 4;
                float v0 = apre[p * 2], v1 = apre[p * 2 + 1];
                __half h0 = __float2half_rn(v0), h1 = __float2half_rn(v1);
                __half l0 = __float2half_rn(v0 - __half2float(h0));
                __half l1 = __float2half_rn(v1 - __half2float(h1));
                __half2 hh = __halves2half2(h0, h1);
                __half2 ll = __halves2half2(l0, l1);
                sm[stn + kp * 136 + am]        = *(uint32_t*)&hh;
                sm[stn + 2176 + kp * 136 + am] = *(uint32_t*)&ll;
            }
        }
    }
    __syncthreads();

    // ---- stage D tile (cols 0..199, stride 201) ----
#pragma unroll
    for (int nt = 0; nt < 8; nt++) {
        const int n = wn * 64 + nt * 8 + (lane & 3) * 2;
        if (n >= 200) continue;
#pragma unroll
        for (int mt = 0; mt < 2; mt++) {
            const int r = wm * 32 + mt * 16 + (lane >> 2);
            const float* c = acc[nt * 2 + mt];
            smf[SM_D + r * 201 + n]           = c[0];
            smf[SM_D + r * 201 + n + 1]       = c[1];
            smf[SM_D + (r + 8) * 201 + n]     = c[2];
            smf[SM_D + (r + 8) * 201 + n + 1] = c[3];
        }
    }
    __syncthreads();

    // ---- decode epilogue ----
    if (t < 128) {
        const bool ok = t < valid;
        const int pos = pos0 + t;
        const int a_g = soffA[s] + pos;
        const int py = pos / W, px = pos - py * W;
        const float gx = px + 0.5f, gy = py + 0.5f;
        const float* Dr = smf + SM_D + t * 201;
        const float* bi = smf + SM_BIAS;

        float dist[4], v16[16];
#pragma unroll
        for (int f = 0; f < 4; f++) {
#pragma unroll
            for (int i = 0; i < 16; i++) v16[i] = Dr[f * 16 + i] + bi[f * 16 + i];
            dist[f] = dfl16(v16);
        }
        if (ok) {
            float x1 = gx - dist[0], y1 = gy - dist[1];
            float x2 = gx + dist[2], y2 = gy + dist[3];
            g_dbox[((size_t)b * 4 + 0) * A_TOT + a_g] = (x1 + x2) * 0.5f * stride;
            g_dbox[((size_t)b * 4 + 1) * A_TOT + a_g] = (y1 + y2) * 0.5f * stride;
            g_dbox[((size_t)b * 4 + 2) * A_TOT + a_g] = (x2 - x1) * stride;
            g_dbox[((size_t)b * 4 + 3) * A_TOT + a_g] = (y2 - y1) * stride;
        }

        float best = -INFINITY; int bcls = 0;
#pragma unroll
        for (int c = 0; c < NCLS; c++) {
            float v = Dr[64 + c] + bi[64 + c];
            if (v > best) { best = v; bcls = c; }
        }
        if (ok) {
            g_maxs[b * A_TOT + a_g] = 1.f / (1.f + expf(-best));
            g_cls[b * A_TOT + a_g]  = bcls;
        }

        if (ok) {
#pragma unroll
            for (int nk = 0; nk < NKPT; nk++) {
                float v = Dr[144 + nk] + bi[144 + nk];
                const int comp = nk % 3;
                float o = (comp == 0) ? (v * 2.f + (gx - 0.5f)) * stride
                        : (comp == 1) ? (v * 2.f + (gy - 0.5f)) * stride
                                      : 1.f / (1.f + expf(-v));
                g_kpts[((size_t)b * NKPT + nk) * A_TOT + a_g] = o;
            }
        }
    }
}

// ---------------------------------------------------------------------------
// Per-batch top-100 via histogram threshold + bitonic sort of candidates.
// Exact lax.top_k semantics: value desc, index asc on ties.
// ---------------------------------------------------------------------------
#define NBIN 4096
#define CANDC 2048

__global__ void __launch_bounds__(1024) topk_k(float* __restrict__ out)
{
    __shared__ int hist[NBIN];
    __shared__ int coarse[256];
    __shared__ unsigned long long cand[CANDC];
    __shared__ int s_cnt, s_T;
    __shared__ int s_idx[MAX_DET];
    __shared__ float s_val[MAX_DET];

    const int b = blockIdx.x;
    const int t = threadIdx.x;
    const float* scores = g_maxs + b * A_TOT;

#pragma unroll
    for (int i = 0; i < NBIN / 1024; i++) hist[t + i * 1024] = 0;
#pragma unroll
    for (int i = 0; i < CANDC / 1024; i++) cand[t + i * 1024] = 0ull;
    if (t == 0) s_cnt = 0;
    __syncthreads();

    // histogram (scores are sigmoid outputs in (0,1))
    for (int i = t; i < A_TOT; i += 1024) {
        int bin = min(NBIN - 1, max(0, (int)(scores[i] * (float)NBIN)));
        atomicAdd(&hist[bin], 1);
    }
    __syncthreads();

    if (t < 256) {
        int sum = 0;
#pragma unroll
        for (int i = 0; i < 16; i++) sum += hist[t * 16 + i];
        coarse[t] = sum;
    }
    __syncthreads();

    if (t == 0) {
        int acc = 0, T = 0;
        int c;
        for (c = 255; c >= 0; c--) {
            if (acc + coarse[c] >= MAX_DET) break;
            acc += coarse[c];
        }
        if (c < 0) { T = 0; }
        else {
            for (int bin = c * 16 + 15; bin >= c * 16; bin--) {
                acc += hist[bin];
                if (acc >= MAX_DET) { T = bin; break; }
                if (bin == c * 16) T = bin;   // safety
            }
        }
        s_T = T;
    }
    __syncthreads();

    const int T = s_T;
    for (int i = t; i < A_TOT; i += 1024) {
        float v = scores[i];
        int bin = min(NBIN - 1, max(0, (int)(v * (float)NBIN)));
        if (bin >= T) {
            int pos = atomicAdd(&s_cnt, 1);
            if (pos < CANDC)
                cand[pos] = ((unsigned long long)__float_as_uint(v) << 32)
                          | (unsigned long long)(A_TOT - 1 - i);
        }
    }
    __syncthreads();

    // bitonic sort CANDC keys descending (pad keys are 0)
    for (int k = 2; k <= CANDC; k <<= 1) {
        for (int j = k >> 1; j > 0; j >>= 1) {
            int idx = ((t & ~(j - 1)) << 1) | (t & (j - 1));
            int ixj = idx | j;
            unsigned long long a = cand[idx], bb2 = cand[ixj];
            bool descBlk = ((idx & k) == 0);
            if ((a < bb2) == descBlk) { cand[idx] = bb2; cand[ixj] = a; }
            __syncthreads();
        }
    }

    if (t < MAX_DET) {
        unsigned long long key = cand[t];
        s_val[t] = __uint_as_float((uint32_t)(key >> 32));
        s_idx[t] = A_TOT - 1 - (int)(key & 0xFFFFFFFFull);
    }
    __syncthreads();

    if (t == 0) {
        int cnt = 0;
        for (int j = 0; j < MAX_DET; j++) cnt += (s_val[j] > CONF) ? 1 : 0;
        out[O_NUM + b] = (float)cnt;
    }
    for (int e = t; e < MAX_DET * 4; e += 1024) {
        int j = e >> 2, c = e & 3;
        out[O_BOX + ((size_t)b * MAX_DET + j) * 4 + c] =
            g_dbox[((size_t)b * 4 + c) * A_TOT + s_idx[j]];
    }
    for (int j = t; j < MAX_DET; j += 1024) {
        out[O_SCORE + b * MAX_DET + j] = s_val[j];
        out[O_CLS   + b * MAX_DET + j] = (float)g_cls[b * A_TOT + s_idx[j]];
    }
    for (int e = t; e < MAX_DET * NKPT; e += 1024) {
        int j = e / NKPT, nk = e - j * NKPT;
        out[O_KPT + ((size_t)b * MAX_DET + j) * NKPT + nk] =
            g_kpts[((size_t)b * NKPT + nk) * A_TOT + s_idx[j]];
    }
}

// ---------------------------------------------------------------------------
extern "C" void kernel_launch(void* const* d_in, const int* in_sizes, int n_in,
                              void* d_out, int out_size)
{
    cudaFuncSetAttribute(gemm_tc, cudaFuncAttributeMaxDynamicSharedMemorySize, SMEM_BYTES);

    pack_k<<<(229376 + 255) / 256, 256>>>(
        (const float*)d_in[3],  (const float*)d_in[4],
        (const float*)d_in[5],  (const float*)d_in[6],
        (const float*)d_in[7],  (const float*)d_in[8],
        (const float*)d_in[9],  (const float*)d_in[10],
        (const float*)d_in[11], (const float*)d_in[12],
        (const float*)d_in[13], (const float*)d_in[14],
        (const float*)d_in[15], (const float*)d_in[16],
        (const float*)d_in[17], (const float*)d_in[18],
        (const float*)d_in[19], (const float*)d_in[20]);

    gemm_tc<<<1072, 512, SMEM_BYTES>>>((const float*)d_in[0],
                                       (const float*)d_in[1],
                                       (const float*)d_in[2]);

    topk_k<<<BS, 1024>>>((float*)d_out);
}

// round 6
// speedup vs baseline: 3.4271x; 1.0235x over previous
#include <cuda_runtime.h>
#include <cuda_fp16.h>
#include <math.h>
#include <stdint.h>

#define BS 16
#define NCLS 80
#define NKPT 51
#define A_TOT 8400
#define MAX_DET 100
#define CONF 0.25f

// output layout (floats)
#define O_NUM   0
#define O_BOX   16
#define O_SCORE 6416
#define O_CLS   8016
#define O_KPT   9616

// device scratch
__device__ __align__(16) __half g_wh[229376];   // [s][n=256][k], hi part
__device__ __align__(16) __half g_wl[229376];   // lo part
__device__ float g_bias[3 * 256];
__device__ float g_dbox[(size_t)BS * 4 * A_TOT];
__device__ float g_kpts[(size_t)BS * NKPT * A_TOT];
__device__ float g_maxs[BS * A_TOT];
__device__ int   g_cls[BS * A_TOT];

// ---------------------------------------------------------------------------
// Pack (single launch): split weights into fp16 hi/lo + bias.
// ---------------------------------------------------------------------------
__global__ void pack_k(const float* __restrict__ w20, const float* __restrict__ b20,
                       const float* __restrict__ w21, const float* __restrict__ b21,
                       const float* __restrict__ w22, const float* __restrict__ b22,
                       const float* __restrict__ w30, const float* __restrict__ b30,
                       const float* __restrict__ w31, const float* __restrict__ b31,
                       const float* __restrict__ w32, const float* __restrict__ b32,
                       const float* __restrict__ w40, const float* __restrict__ b40,
                       const float* __restrict__ w41, const float* __restrict__ b41,
                       const float* __restrict__ w42, const float* __restrict__ b42)
{
    int gidx = blockIdx.x * blockDim.x + threadIdx.x;
    if (gidx >= 229376) return;
    int s, idx, C;
    if (gidx < 32768)       { s = 0; idx = gidx;          C = 128; }
    else if (gidx < 98304)  { s = 1; idx = gidx - 32768;  C = 256; }
    else                    { s = 2; idx = gidx - 98304;  C = 512; }
    const float* w2 = (s == 0) ? w20 : (s == 1) ? w21 : w22;
    const float* b2 = (s == 0) ? b20 : (s == 1) ? b21 : b22;
    const float* w3 = (s == 0) ? w30 : (s == 1) ? w31 : w32;
    const float* b3 = (s == 0) ? b30 : (s == 1) ? b31 : b32;
    const float* w4 = (s == 0) ? w40 : (s == 1) ? w41 : w42;
    const float* b4 = (s == 0) ? b40 : (s == 1) ? b41 : b42;

    int n = idx / C;
    int k = idx - n * C;
    float v = 0.f;
    if (n < 64)        v = w2[n * C + k];
    else if (n < 144)  v = w3[(n - 64) * C + k];
    else if (n < 195)  v = w4[(n - 144) * C + k];
    __half h = __float2half_rn(v);
    g_wh[gidx] = h;
    g_wl[gidx] = __float2half_rn(v - __half2float(h));
    if (k == 0) {
        float bb = 0.f;
        if (n < 64)        bb = b2[n];
        else if (n < 144)  bb = b3[n - 64];
        else if (n < 195)  bb = b4[n - 144];
        g_bias[s * 256 + n] = bb;
    }
}

// ---------------------------------------------------------------------------
__device__ __forceinline__ void mma_f16(float* c, const uint32_t* a,
                                        uint32_t b0, uint32_t b1)
{
    asm volatile(
        "mma.sync.aligned.m16n8k16.row.col.f32.f16.f16.f32 "
        "{%0,%1,%2,%3}, {%4,%5,%6,%7}, {%8,%9}, {%0,%1,%2,%3};"
        : "+f"(c[0]), "+f"(c[1]), "+f"(c[2]), "+f"(c[3])
        : "r"(a[0]), "r"(a[1]), "r"(a[2]), "r"(a[3]), "r"(b0), "r"(b1));
}

__device__ __forceinline__ void ldm_x4(uint32_t* r, uint32_t addr)
{
    asm volatile("ldmatrix.sync.aligned.m8n8.x4.shared.b16 {%0,%1,%2,%3}, [%4];"
                 : "=r"(r[0]), "=r"(r[1]), "=r"(r[2]), "=r"(r[3]) : "r"(addr));
}

__device__ __forceinline__ float dfl16(const float* v) {
    float mx = v[0];
#pragma unroll
    for (int i = 1; i < 16; i++) mx = fmaxf(mx, v[i]);
    float s = 0.f, w = 0.f;
#pragma unroll
    for (int i = 0; i < 16; i++) {
        float e = expf(v[i] - mx);
        s += e;
        w += e * (float)i;
    }
    return w / s;
}

// smem word layout. Row stride = 20 words (40 halves) for A and B regions.
// per stage: A_HI 128x20=2560, A_LO 2560, B_HI 256x20=5120, B_LO 5120 -> 15360
// D tile (128 x 201 fp32 = 25728 words) aliases the stage region after mainloop.
#define ST_WORDS 15360
#define A_LO_W   2560
#define B_HI_W   5120
#define B_LO_W   10240
#define SM_D     0
#define SM_BIAS  30720
#define SM_WORDS 30976
#define SMEM_BYTES (SM_WORDS * 4)      // 123904

// ---------------------------------------------------------------------------
// Fused GEMM (split-fp16 mma.sync, ldmatrix, 2-stage cp.async) + decode.
// 512 threads = 16 warps, warp tile 32(M) x 64(N), K-chunk 32.
// ---------------------------------------------------------------------------
__global__ void __launch_bounds__(512, 1) gemm_tc(const float* __restrict__ x0,
                                                  const float* __restrict__ x1,
                                                  const float* __restrict__ x2)
{
    extern __shared__ uint32_t sm[];
    float* smf = (float*)sm;

    int bid = blockIdx.x;
    int s, rel;
    if (bid < 800)       { s = 0; rel = bid; }
    else if (bid < 1008) { s = 1; rel = bid - 800; }
    else                 { s = 2; rel = bid - 1008; }
    const int tpbA[3]  = {50, 13, 4};
    const int CsA[3]   = {128, 256, 512};
    const int HWA[3]   = {6400, 1600, 400};
    const int soffA[3] = {0, 6400, 8000};
    const int WA[3]    = {80, 40, 20};
    const int woffA[3] = {0, 32768, 98304};
    const float strA[3] = {8.f, 16.f, 32.f};

    const int C = CsA[s], HW = HWA[s], W = WA[s];
    const float stride = strA[s];
    const int b    = rel / tpbA[s];
    const int tile = rel - b * tpbA[s];
    const int pos0 = tile * 128;
    const int valid = min(128, HW - pos0);

    const float* xsel = (s == 0) ? x0 : (s == 1) ? x1 : x2;
    const float* xb = xsel + (size_t)b * C * HW + pos0;
    const __half* wh = g_wh + woffA[s];
    const __half* wl = g_wl + woffA[s];

    const int t = threadIdx.x;
    const int lane = t & 31;
    const int wid = t >> 5;
    const int wm = wid & 3;
    const int wn = wid >> 2;

    const uint32_t smb = (uint32_t)__cvta_generic_to_shared(sm);

    for (int i = t; i < 256; i += 512) smf[SM_BIAS + i] = g_bias[s * 256 + i];

    float acc[16][4];
#pragma unroll
    for (int i = 0; i < 16; i++)
#pragma unroll
        for (int j = 0; j < 4; j++) acc[i][j] = 0.f;

    // A loader: thread handles 8 consecutive channels for one anchor row
    const int am   = t & 127;
    const int akp0 = t >> 7;          // channel group 0..3 (8 ch each)
    // B loader
    const int bn   = t >> 2;
    const int boff = t & 3;

    const int nkt = C >> 5;

    // ---- prologue: chunk 0 ----
    {
#pragma unroll
        for (int i = 0; i < 2; i++) {
            const int n = bn + i * 128;
            const uint32_t dsth = smb + (B_HI_W + n * 20 + boff * 4) * 4;
            const uint32_t dstl = smb + (B_LO_W + n * 20 + boff * 4) * 4;
            asm volatile("cp.async.cg.shared.global [%0], [%1], 16;"
                         :: "r"(dsth), "l"(wh + (size_t)n * C + boff * 8) : "memory");
            asm volatile("cp.async.cg.shared.global [%0], [%1], 16;"
                         :: "r"(dstl), "l"(wl + (size_t)n * C + boff * 8) : "memory");
        }
        asm volatile("cp.async.commit_group;" ::: "memory");
        // A chunk 0: 8 consecutive channels -> one uint4 hi + one uint4 lo
        float v[8];
#pragma unroll
        for (int j = 0; j < 8; j++)
            v[j] = (am < valid) ? xb[(size_t)(akp0 * 8 + j) * HW + am] : 0.f;
        uint32_t hw4[4], lw4[4];
#pragma unroll
        for (int p = 0; p < 4; p++) {
            __half h0 = __float2half_rn(v[2*p]), h1 = __float2half_rn(v[2*p+1]);
            __half l0 = __float2half_rn(v[2*p] - __half2float(h0));
            __half l1 = __float2half_rn(v[2*p+1] - __half2float(h1));
            __half2 hh = __halves2half2(h0, h1);
            __half2 ll = __halves2half2(l0, l1);
            hw4[p] = *(uint32_t*)&hh;
            lw4[p] = *(uint32_t*)&ll;
        }
        *(uint4*)&sm[am * 20 + akp0 * 4]          = *(uint4*)hw4;
        *(uint4*)&sm[A_LO_W + am * 20 + akp0 * 4] = *(uint4*)lw4;
    }

    for (int kt = 0; kt < nkt; kt++) {
        const int st = (kt & 1) ? ST_WORDS : 0;
        asm volatile("cp.async.wait_group 0;" ::: "memory");
        __syncthreads();

        float apre[8];
        const bool pf = (kt + 1 < nkt);
        const int stn = ((kt + 1) & 1) ? ST_WORDS : 0;
        if (pf) {
            const int c1 = (kt + 1) << 5;
#pragma unroll
            for (int i = 0; i < 2; i++) {
                const int n = bn + i * 128;
                const uint32_t dsth = smb + (stn + B_HI_W + n * 20 + boff * 4) * 4;
                const uint32_t dstl = smb + (stn + B_LO_W + n * 20 + boff * 4) * 4;
                asm volatile("cp.async.cg.shared.global [%0], [%1], 16;"
                             :: "r"(dsth), "l"(wh + (size_t)n * C + c1 + boff * 8) : "memory");
                asm volatile("cp.async.cg.shared.global [%0], [%1], 16;"
                             :: "r"(dstl), "l"(wl + (size_t)n * C + c1 + boff * 8) : "memory");
            }
            asm volatile("cp.async.commit_group;" ::: "memory");
#pragma unroll
            for (int j = 0; j < 8; j++)
                apre[j] = (am < valid) ? xb[(size_t)(c1 + akp0 * 8 + j) * HW + am] : 0.f;
        }

        // ---- compute current chunk (ldmatrix fragments) ----
#pragma unroll
        for (int k16 = 0; k16 < 2; k16++) {
            uint32_t ah[2][4], al[2][4];
            const uint32_t acol = k16 * 32 + (lane >> 4) * 16;   // bytes in row
#pragma unroll
            for (int mt = 0; mt < 2; mt++) {
                const int row = wm * 32 + mt * 16 + (lane & 15);
                const uint32_t ba = smb + (st + row * 20) * 4 + acol;
                ldm_x4(ah[mt], ba);
                ldm_x4(al[mt], ba + A_LO_W * 4);
            }
            const int brow = (lane & 7) + ((lane >> 4) << 3);
            const uint32_t bcol = ((lane >> 3) & 1) * 16 + k16 * 32;
#pragma unroll
            for (int ntp = 0; ntp < 4; ntp++) {
                const int nb = wn * 64 + ntp * 16 + brow;
                uint32_t bh[4], bl[4];
                const uint32_t bb = smb + (st + B_HI_W + nb * 20) * 4 + bcol;
                ldm_x4(bh, bb);
                ldm_x4(bl, bb + (B_LO_W - B_HI_W) * 4);
#pragma unroll
                for (int h = 0; h < 2; h++) {
                    const int nt = ntp * 2 + h;
#pragma unroll
                    for (int mt = 0; mt < 2; mt++) {
                        float* c = acc[nt * 2 + mt];
                        mma_f16(c, ah[mt], bh[2*h], bh[2*h+1]);
                        mma_f16(c, ah[mt], bl[2*h], bl[2*h+1]);
                        mma_f16(c, al[mt], bh[2*h], bh[2*h+1]);
                    }
                }
            }
        }

        if (pf) {
            uint32_t hw4[4], lw4[4];
#pragma unroll
            for (int p = 0; p < 4; p++) {
                __half h0 = __float2half_rn(apre[2*p]), h1 = __float2half_rn(apre[2*p+1]);
                __half l0 = __float2half_rn(apre[2*p] - __half2float(h0));
                __half l1 = __float2half_rn(apre[2*p+1] - __half2float(h1));
                __half2 hh = __halves2half2(h0, h1);
                __half2 ll = __halves2half2(l0, l1);
                hw4[p] = *(uint32_t*)&hh;
                lw4[p] = *(uint32_t*)&ll;
            }
            *(uint4*)&sm[stn + am * 20 + akp0 * 4]          = *(uint4*)hw4;
            *(uint4*)&sm[stn + A_LO_W + am * 20 + akp0 * 4] = *(uint4*)lw4;
        }
    }
    __syncthreads();   // mainloop done; stage smem now reused as D tile

    // ---- stage D tile (cols 0..199, stride 201) ----
#pragma unroll
    for (int nt = 0; nt < 8; nt++) {
        const int n = wn * 64 + nt * 8 + (lane & 3) * 2;
        if (n >= 200) continue;
#pragma unroll
        for (int mt = 0; mt < 2; mt++) {
            const int r = wm * 32 + mt * 16 + (lane >> 2);
            const float* c = acc[nt * 2 + mt];
            smf[SM_D + r * 201 + n]           = c[0];
            smf[SM_D + r * 201 + n + 1]       = c[1];
            smf[SM_D + (r + 8) * 201 + n]     = c[2];
            smf[SM_D + (r + 8) * 201 + n + 1] = c[3];
        }
    }
    __syncthreads();

    // ---- decode epilogue ----
    if (t < 128) {
        const bool ok = t < valid;
        const int pos = pos0 + t;
        const int a_g = soffA[s] + pos;
        const int py = pos / W, px = pos - py * W;
        const float gx = px + 0.5f, gy = py + 0.5f;
        const float* Dr = smf + SM_D + t * 201;
        const float* bi = smf + SM_BIAS;

        float dist[4], v16[16];
#pragma unroll
        for (int f = 0; f < 4; f++) {
#pragma unroll
            for (int i = 0; i < 16; i++) v16[i] = Dr[f * 16 + i] + bi[f * 16 + i];
            dist[f] = dfl16(v16);
        }
        if (ok) {
            float x1 = gx - dist[0], y1 = gy - dist[1];
            float x2 = gx + dist[2], y2 = gy + dist[3];
            g_dbox[((size_t)b * 4 + 0) * A_TOT + a_g] = (x1 + x2) * 0.5f * stride;
            g_dbox[((size_t)b * 4 + 1) * A_TOT + a_g] = (y1 + y2) * 0.5f * stride;
            g_dbox[((size_t)b * 4 + 2) * A_TOT + a_g] = (x2 - x1) * stride;
            g_dbox[((size_t)b * 4 + 3) * A_TOT + a_g] = (y2 - y1) * stride;
        }

        float best = -INFINITY; int bcls = 0;
#pragma unroll
        for (int c = 0; c < NCLS; c++) {
            float v = Dr[64 + c] + bi[64 + c];
            if (v > best) { best = v; bcls = c; }
        }
        if (ok) {
            g_maxs[b * A_TOT + a_g] = 1.f / (1.f + expf(-best));
            g_cls[b * A_TOT + a_g]  = bcls;
        }

        if (ok) {
#pragma unroll
            for (int nk = 0; nk < NKPT; nk++) {
                float v = Dr[144 + nk] + bi[144 + nk];
                const int comp = nk % 3;
                float o = (comp == 0) ? (v * 2.f + (gx - 0.5f)) * stride
                        : (comp == 1) ? (v * 2.f + (gy - 0.5f)) * stride
                                      : 1.f / (1.f + expf(-v));
                g_kpts[((size_t)b * NKPT + nk) * A_TOT + a_g] = o;
            }
        }
    }
}

// ---------------------------------------------------------------------------
// Per-batch top-100 via histogram threshold + bitonic sort of candidates.
// ---------------------------------------------------------------------------
#define NBIN 4096
#define CANDC 2048

__global__ void __launch_bounds__(1024) topk_k(float* __restrict__ out)
{
    __shared__ int hist[NBIN];
    __shared__ int coarse[256];
    __shared__ unsigned long long cand[CANDC];
    __shared__ int s_cnt, s_T;
    __shared__ int s_idx[MAX_DET];
    __shared__ float s_val[MAX_DET];

    const int b = blockIdx.x;
    const int t = threadIdx.x;
    const float* scores = g_maxs + b * A_TOT;

#pragma unroll
    for (int i = 0; i < NBIN / 1024; i++) hist[t + i * 1024] = 0;
#pragma unroll
    for (int i = 0; i < CANDC / 1024; i++) cand[t + i * 1024] = 0ull;
    if (t == 0) s_cnt = 0;
    __syncthreads();

    for (int i = t; i < A_TOT; i += 1024) {
        int bin = min(NBIN - 1, max(0, (int)(scores[i] * (float)NBIN)));
        atomicAdd(&hist[bin], 1);
    }
    __syncthreads();

    if (t < 256) {
        int sum = 0;
#pragma unroll
        for (int i = 0; i < 16; i++) sum += hist[t * 16 + i];
        coarse[t] = sum;
    }
    __syncthreads();

    if (t == 0) {
        int acc = 0, T = 0;
        int c;
        for (c = 255; c >= 0; c--) {
            if (acc + coarse[c] >= MAX_DET) break;
            acc += coarse[c];
        }
        if (c < 0) { T = 0; }
        else {
            for (int bin = c * 16 + 15; bin >= c * 16; bin--) {
                acc += hist[bin];
                if (acc >= MAX_DET) { T = bin; break; }
                if (bin == c * 16) T = bin;
            }
        }
        s_T = T;
    }
    __syncthreads();

    const int T = s_T;
    for (int i = t; i < A_TOT; i += 1024) {
        float v = scores[i];
        int bin = min(NBIN - 1, max(0, (int)(v * (float)NBIN)));
        if (bin >= T) {
            int pos = atomicAdd(&s_cnt, 1);
            if (pos < CANDC)
                cand[pos] = ((unsigned long long)__float_as_uint(v) << 32)
                          | (unsigned long long)(A_TOT - 1 - i);
        }
    }
    __syncthreads();

    for (int k = 2; k <= CANDC; k <<= 1) {
        for (int j = k >> 1; j > 0; j >>= 1) {
            int idx = ((t & ~(j - 1)) << 1) | (t & (j - 1));
            int ixj = idx | j;
            unsigned long long a = cand[idx], bb2 = cand[ixj];
            bool descBlk = ((idx & k) == 0);
            if ((a < bb2) == descBlk) { cand[idx] = bb2; cand[ixj] = a; }
            __syncthreads();
        }
    }

    if (t < MAX_DET) {
        unsigned long long key = cand[t];
        s_val[t] = __uint_as_float((uint32_t)(key >> 32));
        s_idx[t] = A_TOT - 1 - (int)(key & 0xFFFFFFFFull);
    }
    __syncthreads();

    if (t == 0) {
        int cnt = 0;
        for (int j = 0; j < MAX_DET; j++) cnt += (s_val[j] > CONF) ? 1 : 0;
        out[O_NUM + b] = (float)cnt;
    }
    for (int e = t; e < MAX_DET * 4; e += 1024) {
        int j = e >> 2, c = e & 3;
        out[O_BOX + ((size_t)b * MAX_DET + j) * 4 + c] =
            g_dbox[((size_t)b * 4 + c) * A_TOT + s_idx[j]];
    }
    for (int j = t; j < MAX_DET; j += 1024) {
        out[O_SCORE + b * MAX_DET + j] = s_val[j];
        out[O_CLS   + b * MAX_DET + j] = (float)g_cls[b * A_TOT + s_idx[j]];
    }
    for (int e = t; e < MAX_DET * NKPT; e += 1024) {
        int j = e / NKPT, nk = e - j * NKPT;
        out[O_KPT + ((size_t)b * MAX_DET + j) * NKPT + nk] =
            g_kpts[((size_t)b * NKPT + nk) * A_TOT + s_idx[j]];
    }
}

// ---------------------------------------------------------------------------
extern "C" void kernel_launch(void* const* d_in, const int* in_sizes, int n_in,
                              void* d_out, int out_size)
{
    cudaFuncSetAttribute(gemm_tc, cudaFuncAttributeMaxDynamicSharedMemorySize, SMEM_BYTES);

    pack_k<<<(229376 + 255) / 256, 256>>>(
        (const float*)d_in[3],  (const float*)d_in[4],
        (const float*)d_in[5],  (const float*)d_in[6],
        (const float*)d_in[7],  (const float*)d_in[8],
        (const float*)d_in[9],  (const float*)d_in[10],
        (const float*)d_in[11], (const float*)d_in[12],
        (const float*)d_in[13], (const float*)d_in[14],
        (const float*)d_in[15], (const float*)d_in[16],
        (const float*)d_in[17], (const float*)d_in[18],
        (const float*)d_in[19], (const float*)d_in[20]);

    gemm_tc<<<1072, 512, SMEM_BYTES>>>((const float*)d_in[0],
                                       (const float*)d_in[1],
                                       (const float*)d_in[2]);

    topk_k<<<BS, 1024>>>((float*)d_out);
}

// round 7
// speedup vs baseline: 3.6540x; 1.0662x over previous
#include <cuda_runtime.h>
#include <cuda_fp16.h>
#include <math.h>
#include <stdint.h>

#define BS 16
#define NCLS 80
#define NKPT 51
#define A_TOT 8400
#define MAX_DET 100
#define CONF 0.25f

// output layout (floats)
#define O_NUM   0
#define O_BOX   16
#define O_SCORE 6416
#define O_CLS   8016
#define O_KPT   9616

// device scratch
__device__ __align__(16) __half g_wh[229376];   // [s][n=256][k], hi part
__device__ __align__(16) __half g_wl[229376];   // lo part
__device__ float g_bias[3 * 256];
__device__ float g_dbox[(size_t)BS * 4 * A_TOT];
__device__ float g_kpts[(size_t)BS * NKPT * A_TOT];
__device__ float g_maxs[BS * A_TOT];
__device__ int   g_cls[BS * A_TOT];

// ---------------------------------------------------------------------------
// Pack (single launch): split weights into fp16 hi/lo + bias.
// ---------------------------------------------------------------------------
__global__ void pack_k(const float* __restrict__ w20, const float* __restrict__ b20,
                       const float* __restrict__ w21, const float* __restrict__ b21,
                       const float* __restrict__ w22, const float* __restrict__ b22,
                       const float* __restrict__ w30, const float* __restrict__ b30,
                       const float* __restrict__ w31, const float* __restrict__ b31,
                       const float* __restrict__ w32, const float* __restrict__ b32,
                       const float* __restrict__ w40, const float* __restrict__ b40,
                       const float* __restrict__ w41, const float* __restrict__ b41,
                       const float* __restrict__ w42, const float* __restrict__ b42)
{
    int gidx = blockIdx.x * blockDim.x + threadIdx.x;
    if (gidx >= 229376) return;
    int s, idx, C;
    if (gidx < 32768)       { s = 0; idx = gidx;          C = 128; }
    else if (gidx < 98304)  { s = 1; idx = gidx - 32768;  C = 256; }
    else                    { s = 2; idx = gidx - 98304;  C = 512; }
    const float* w2 = (s == 0) ? w20 : (s == 1) ? w21 : w22;
    const float* b2 = (s == 0) ? b20 : (s == 1) ? b21 : b22;
    const float* w3 = (s == 0) ? w30 : (s == 1) ? w31 : w32;
    const float* b3 = (s == 0) ? b30 : (s == 1) ? b31 : b32;
    const float* w4 = (s == 0) ? w40 : (s == 1) ? w41 : w42;
    const float* b4 = (s == 0) ? b40 : (s == 1) ? b41 : b42;

    int n = idx / C;
    int k = idx - n * C;
    float v = 0.f;
    if (n < 64)        v = w2[n * C + k];
    else if (n < 144)  v = w3[(n - 64) * C + k];
    else if (n < 195)  v = w4[(n - 144) * C + k];
    __half h = __float2half_rn(v);
    g_wh[gidx] = h;
    g_wl[gidx] = __float2half_rn(v - __half2float(h));
    if (k == 0) {
        float bb = 0.f;
        if (n < 64)        bb = b2[n];
        else if (n < 144)  bb = b3[n - 64];
        else if (n < 195)  bb = b4[n - 144];
        g_bias[s * 256 + n] = bb;
    }
}

// ---------------------------------------------------------------------------
__device__ __forceinline__ void mma_f16(float* c, const uint32_t* a,
                                        uint32_t b0, uint32_t b1)
{
    asm volatile(
        "mma.sync.aligned.m16n8k16.row.col.f32.f16.f16.f32 "
        "{%0,%1,%2,%3}, {%4,%5,%6,%7}, {%8,%9}, {%0,%1,%2,%3};"
        : "+f"(c[0]), "+f"(c[1]), "+f"(c[2]), "+f"(c[3])
        : "r"(a[0]), "r"(a[1]), "r"(a[2]), "r"(a[3]), "r"(b0), "r"(b1));
}

__device__ __forceinline__ void ldm_x4(uint32_t* r, uint32_t addr)
{
    asm volatile("ldmatrix.sync.aligned.m8n8.x4.shared.b16 {%0,%1,%2,%3}, [%4];"
                 : "=r"(r[0]), "=r"(r[1]), "=r"(r[2]), "=r"(r[3]) : "r"(addr));
}

__device__ __forceinline__ float dfl16(const float* v) {
    float mx = v[0];
#pragma unroll
    for (int i = 1; i < 16; i++) mx = fmaxf(mx, v[i]);
    float s = 0.f, w = 0.f;
#pragma unroll
    for (int i = 0; i < 16; i++) {
        float e = expf(v[i] - mx);
        s += e;
        w += e * (float)i;
    }
    return w / s;
}

// smem word layout. Row stride = 20 words (40 halves) for A and B regions.
// per stage: A_HI 128x20=2560, A_LO 2560, B_HI 208x20=4160, B_LO 4160 -> 13440
// D tile (128 x 201 fp32 = 25728 words) aliases the two stages after mainloop.
#define ST_WORDS 13440
#define A_LO_W   2560
#define B_HI_W   5120
#define B_LO_W   9280
#define SM_D     0
#define SM_BIAS  26880
#define SM_WORDS 27136
#define SMEM_BYTES (SM_WORDS * 4)      // 108544

// ---------------------------------------------------------------------------
// Fused GEMM (split-fp16 mma.sync, ldmatrix, 2-stage cp.async) + decode.
// 512 threads = 16 warps. Warps wn<3: 64 N-cols; wn==3: 8 N-cols (192..199).
// ---------------------------------------------------------------------------
__global__ void __launch_bounds__(512, 1) gemm_tc(const float* __restrict__ x0,
                                                  const float* __restrict__ x1,
                                                  const float* __restrict__ x2)
{
    extern __shared__ uint32_t sm[];
    float* smf = (float*)sm;

    int bid = blockIdx.x;
    int s, rel;
    if (bid < 800)       { s = 0; rel = bid; }
    else if (bid < 1008) { s = 1; rel = bid - 800; }
    else                 { s = 2; rel = bid - 1008; }
    const int tpbA[3]  = {50, 13, 4};
    const int CsA[3]   = {128, 256, 512};
    const int HWA[3]   = {6400, 1600, 400};
    const int soffA[3] = {0, 6400, 8000};
    const int WA[3]    = {80, 40, 20};
    const int woffA[3] = {0, 32768, 98304};
    const float strA[3] = {8.f, 16.f, 32.f};

    const int C = CsA[s], HW = HWA[s], W = WA[s];
    const float stride = strA[s];
    const int b    = rel / tpbA[s];
    const int tile = rel - b * tpbA[s];
    const int pos0 = tile * 128;
    const int valid = min(128, HW - pos0);

    const float* xsel = (s == 0) ? x0 : (s == 1) ? x1 : x2;
    const float* xb = xsel + (size_t)b * C * HW + pos0;
    const __half* wh = g_wh + woffA[s];
    const __half* wl = g_wl + woffA[s];

    const int t = threadIdx.x;
    const int lane = t & 31;
    const int wid = t >> 5;
    const int wm = wid & 3;
    const int wn = wid >> 2;

    const uint32_t smb = (uint32_t)__cvta_generic_to_shared(sm);

    for (int i = t; i < 256; i += 512) smf[SM_BIAS + i] = g_bias[s * 256 + i];

    float acc[16][4];
#pragma unroll
    for (int i = 0; i < 16; i++)
#pragma unroll
        for (int j = 0; j < 4; j++) acc[i][j] = 0.f;

    const int am   = t & 127;
    const int akp0 = t >> 7;          // channel group 0..3 (8 ch each)
    const int bn   = t >> 2;          // B loader row base
    const int boff = t & 3;

    const int nkt = C >> 5;

    // ---- prologue: chunk 0 ----
    {
#pragma unroll
        for (int i = 0; i < 2; i++) {
            const int n = bn + i * 128;
            if (n < 208) {
                const uint32_t dsth = smb + (B_HI_W + n * 20 + boff * 4) * 4;
                const uint32_t dstl = smb + (B_LO_W + n * 20 + boff * 4) * 4;
                asm volatile("cp.async.cg.shared.global [%0], [%1], 16;"
                             :: "r"(dsth), "l"(wh + (size_t)n * C + boff * 8) : "memory");
                asm volatile("cp.async.cg.shared.global [%0], [%1], 16;"
                             :: "r"(dstl), "l"(wl + (size_t)n * C + boff * 8) : "memory");
            }
        }
        asm volatile("cp.async.commit_group;" ::: "memory");
        float v[8];
#pragma unroll
        for (int j = 0; j < 8; j++)
            v[j] = (am < valid) ? xb[(size_t)(akp0 * 8 + j) * HW + am] : 0.f;
        uint32_t hw4[4], lw4[4];
#pragma unroll
        for (int p = 0; p < 4; p++) {
            __half h0 = __float2half_rn(v[2*p]), h1 = __float2half_rn(v[2*p+1]);
            __half l0 = __float2half_rn(v[2*p] - __half2float(h0));
            __half l1 = __float2half_rn(v[2*p+1] - __half2float(h1));
            __half2 hh = __halves2half2(h0, h1);
            __half2 ll = __halves2half2(l0, l1);
            hw4[p] = *(uint32_t*)&hh;
            lw4[p] = *(uint32_t*)&ll;
        }
        *(uint4*)&sm[am * 20 + akp0 * 4]          = *(uint4*)hw4;
        *(uint4*)&sm[A_LO_W + am * 20 + akp0 * 4] = *(uint4*)lw4;
    }

    for (int kt = 0; kt < nkt; kt++) {
        const int st = (kt & 1) ? ST_WORDS : 0;
        asm volatile("cp.async.wait_group 0;" ::: "memory");
        __syncthreads();

        float apre[8];
        const bool pf = (kt + 1 < nkt);
        const int stn = ((kt + 1) & 1) ? ST_WORDS : 0;
        if (pf) {
            const int c1 = (kt + 1) << 5;
#pragma unroll
            for (int i = 0; i < 2; i++) {
                const int n = bn + i * 128;
                if (n < 208) {
                    const uint32_t dsth = smb + (stn + B_HI_W + n * 20 + boff * 4) * 4;
                    const uint32_t dstl = smb + (stn + B_LO_W + n * 20 + boff * 4) * 4;
                    asm volatile("cp.async.cg.shared.global [%0], [%1], 16;"
                                 :: "r"(dsth), "l"(wh + (size_t)n * C + c1 + boff * 8) : "memory");
                    asm volatile("cp.async.cg.shared.global [%0], [%1], 16;"
                                 :: "r"(dstl), "l"(wl + (size_t)n * C + c1 + boff * 8) : "memory");
                }
            }
            asm volatile("cp.async.commit_group;" ::: "memory");
#pragma unroll
            for (int j = 0; j < 8; j++)
                apre[j] = (am < valid) ? xb[(size_t)(c1 + akp0 * 8 + j) * HW + am] : 0.f;
        }

        // ---- compute current chunk ----
#pragma unroll
        for (int k16 = 0; k16 < 2; k16++) {
            uint32_t ah[2][4], al[2][4];
            const uint32_t acol = k16 * 32 + (lane >> 4) * 16;
#pragma unroll
            for (int mt = 0; mt < 2; mt++) {
                const int row = wm * 32 + mt * 16 + (lane & 15);
                const uint32_t ba = smb + (st + row * 20) * 4 + acol;
                ldm_x4(ah[mt], ba);
                ldm_x4(al[mt], ba + A_LO_W * 4);
            }
            const int brow = (lane & 7) + ((lane >> 4) << 3);
            const uint32_t bcol = ((lane >> 3) & 1) * 16 + k16 * 32;
            if (wn < 3) {
#pragma unroll
                for (int ntp = 0; ntp < 4; ntp++) {
                    const int nb = wn * 64 + ntp * 16 + brow;
                    uint32_t bh[4], bl[4];
                    const uint32_t bbp = smb + (st + B_HI_W + nb * 20) * 4 + bcol;
                    ldm_x4(bh, bbp);
                    ldm_x4(bl, bbp + (B_LO_W - B_HI_W) * 4);
#pragma unroll
                    for (int h = 0; h < 2; h++) {
                        const int nt = ntp * 2 + h;
#pragma unroll
                        for (int mt = 0; mt < 2; mt++) {
                            float* c = acc[nt * 2 + mt];
                            mma_f16(c, ah[mt], bh[2*h], bh[2*h+1]);
                            mma_f16(c, ah[mt], bl[2*h], bl[2*h+1]);
                            mma_f16(c, al[mt], bh[2*h], bh[2*h+1]);
                        }
                    }
                }
            } else {
                const int nb = 192 + brow;
                uint32_t bh[4], bl[4];
                const uint32_t bbp = smb + (st + B_HI_W + nb * 20) * 4 + bcol;
                ldm_x4(bh, bbp);
                ldm_x4(bl, bbp + (B_LO_W - B_HI_W) * 4);
#pragma unroll
                for (int mt = 0; mt < 2; mt++) {
                    float* c = acc[mt];
                    mma_f16(c, ah[mt], bh[0], bh[1]);
                    mma_f16(c, ah[mt], bl[0], bl[1]);
                    mma_f16(c, al[mt], bh[0], bh[1]);
                }
            }
        }

        if (pf) {
            uint32_t hw4[4], lw4[4];
#pragma unroll
            for (int p = 0; p < 4; p++) {
                __half h0 = __float2half_rn(apre[2*p]), h1 = __float2half_rn(apre[2*p+1]);
                __half l0 = __float2half_rn(apre[2*p] - __half2float(h0));
                __half l1 = __float2half_rn(apre[2*p+1] - __half2float(h1));
                __half2 hh = __halves2half2(h0, h1);
                __half2 ll = __halves2half2(l0, l1);
                hw4[p] = *(uint32_t*)&hh;
                lw4[p] = *(uint32_t*)&ll;
            }
            *(uint4*)&sm[stn + am * 20 + akp0 * 4]          = *(uint4*)hw4;
            *(uint4*)&sm[stn + A_LO_W + am * 20 + akp0 * 4] = *(uint4*)lw4;
        }
    }
    __syncthreads();   // mainloop done; stage smem reused as D tile

    // ---- stage D tile (cols 0..199, stride 201) ----
#pragma unroll
    for (int nt = 0; nt < 8; nt++) {
        const int n = wn * 64 + nt * 8 + (lane & 3) * 2;
        if (n >= 200) continue;
#pragma unroll
        for (int mt = 0; mt < 2; mt++) {
            const int r = wm * 32 + mt * 16 + (lane >> 2);
            const float* c = acc[nt * 2 + mt];
            smf[SM_D + r * 201 + n]           = c[0];
            smf[SM_D + r * 201 + n + 1]       = c[1];
            smf[SM_D + (r + 8) * 201 + n]     = c[2];
            smf[SM_D + (r + 8) * 201 + n + 1] = c[3];
        }
    }
    __syncthreads();

    // ---- decode epilogue: 4 threads per anchor ----
    {
        const int ar  = t >> 2;      // anchor row 0..127
        const int sub = t & 3;
        const bool ok = ar < valid;
        const int pos = pos0 + ar;
        const int a_g = soffA[s] + pos;
        const int py = pos / W, px = pos - py * W;
        const float gx = px + 0.5f, gy = py + 0.5f;
        const float* Dr = smf + SM_D + ar * 201;
        const float* bi = smf + SM_BIAS;
        const unsigned msk = 0xffffffffu;

        // DFL: each sub-thread does one of the 4 softmaxes
        float v16[16];
#pragma unroll
        for (int i = 0; i < 16; i++) v16[i] = Dr[sub * 16 + i] + bi[sub * 16 + i];
        float d = dfl16(v16);
        const float d0 = __shfl_sync(msk, d, 0, 4);
        const float d1 = __shfl_sync(msk, d, 1, 4);
        const float d2 = __shfl_sync(msk, d, 2, 4);
        const float d3 = __shfl_sync(msk, d, 3, 4);
        if (ok && sub == 0) {
            float x1 = gx - d0, y1 = gy - d1;
            float x2 = gx + d2, y2 = gy + d3;
            g_dbox[((size_t)b * 4 + 0) * A_TOT + a_g] = (x1 + x2) * 0.5f * stride;
            g_dbox[((size_t)b * 4 + 1) * A_TOT + a_g] = (y1 + y2) * 0.5f * stride;
            g_dbox[((size_t)b * 4 + 2) * A_TOT + a_g] = (x2 - x1) * stride;
            g_dbox[((size_t)b * 4 + 3) * A_TOT + a_g] = (y2 - y1) * stride;
        }

        // class argmax: 20 classes per sub-thread, combine over group of 4
        float best = -INFINITY; int bcls = 0;
#pragma unroll
        for (int c = 0; c < 20; c++) {
            const int cc = sub * 20 + c;
            float v = Dr[64 + cc] + bi[64 + cc];
            if (v > best) { best = v; bcls = cc; }
        }
#pragma unroll
        for (int o = 2; o > 0; o >>= 1) {
            float v2 = __shfl_down_sync(msk, best, o, 4);
            int   i2 = __shfl_down_sync(msk, bcls, o, 4);
            if (v2 > best || (v2 == best && i2 < bcls)) { best = v2; bcls = i2; }
        }
        if (ok && sub == 0) {
            g_maxs[b * A_TOT + a_g] = 1.f / (1.f + expf(-best));
            g_cls[b * A_TOT + a_g]  = bcls;
        }

        // keypoints: nk = sub, sub+4, ...
        if (ok) {
            for (int nk = sub; nk < NKPT; nk += 4) {
                float v = Dr[144 + nk] + bi[144 + nk];
                const int comp = nk % 3;
                float o = (comp == 0) ? (v * 2.f + (gx - 0.5f)) * stride
                        : (comp == 1) ? (v * 2.f + (gy - 0.5f)) * stride
                                      : 1.f / (1.f + expf(-v));
                g_kpts[((size_t)b * NKPT + nk) * A_TOT + a_g] = o;
            }
        }
    }
}

// ---------------------------------------------------------------------------
// Per-batch top-100 via histogram threshold + bitonic sort of candidates.
// ---------------------------------------------------------------------------
#define NBIN 4096
#define CANDC 2048

__global__ void __launch_bounds__(1024) topk_k(float* __restrict__ out)
{
    __shared__ int hist[NBIN];
    __shared__ int coarse[256];
    __shared__ unsigned long long cand[CANDC];
    __shared__ int s_cnt, s_T;
    __shared__ int s_idx[MAX_DET];
    __shared__ float s_val[MAX_DET];

    const int b = blockIdx.x;
    const int t = threadIdx.x;
    const float* scores = g_maxs + b * A_TOT;

#pragma unroll
    for (int i = 0; i < NBIN / 1024; i++) hist[t + i * 1024] = 0;
#pragma unroll
    for (int i = 0; i < CANDC / 1024; i++) cand[t + i * 1024] = 0ull;
    if (t == 0) s_cnt = 0;
    __syncthreads();

    for (int i = t; i < A_TOT; i += 1024) {
        int bin = min(NBIN - 1, max(0, (int)(scores[i] * (float)NBIN)));
        atomicAdd(&hist[bin], 1);
    }
    __syncthreads();

    if (t < 256) {
        int sum = 0;
#pragma unroll
        for (int i = 0; i < 16; i++) sum += hist[t * 16 + i];
        coarse[t] = sum;
    }
    __syncthreads();

    if (t == 0) {
        int acc = 0, T = 0;
        int c;
        for (c = 255; c >= 0; c--) {
            if (acc + coarse[c] >= MAX_DET) break;
            acc += coarse[c];
        }
        if (c < 0) { T = 0; }
        else {
            for (int bin = c * 16 + 15; bin >= c * 16; bin--) {
                acc += hist[bin];
                if (acc >= MAX_DET) { T = bin; break; }
                if (bin == c * 16) T = bin;
            }
        }
        s_T = T;
    }
    __syncthreads();

    const int T = s_T;
    for (int i = t; i < A_TOT; i += 1024) {
        float v = scores[i];
        int bin = min(NBIN - 1, max(0, (int)(v * (float)NBIN)));
        if (bin >= T) {
            int pos = atomicAdd(&s_cnt, 1);
            if (pos < CANDC)
                cand[pos] = ((unsigned long long)__float_as_uint(v) << 32)
                          | (unsigned long long)(A_TOT - 1 - i);
        }
    }
    __syncthreads();

    for (int k = 2; k <= CANDC; k <<= 1) {
        for (int j = k >> 1; j > 0; j >>= 1) {
            int idx = ((t & ~(j - 1)) << 1) | (t & (j - 1));
            int ixj = idx | j;
            unsigned long long a = cand[idx], bb2 = cand[ixj];
            bool descBlk = ((idx & k) == 0);
            if ((a < bb2) == descBlk) { cand[idx] = bb2; cand[ixj] = a; }
            __syncthreads();
        }
    }

    if (t < MAX_DET) {
        unsigned long long key = cand[t];
        s_val[t] = __uint_as_float((uint32_t)(key >> 32));
        s_idx[t] = A_TOT - 1 - (int)(key & 0xFFFFFFFFull);
    }
    __syncthreads();

    if (t == 0) {
        int cnt = 0;
        for (int j = 0; j < MAX_DET; j++) cnt += (s_val[j] > CONF) ? 1 : 0;
        out[O_NUM + b] = (float)cnt;
    }
    for (int e = t; e < MAX_DET * 4; e += 1024) {
        int j = e >> 2, c = e & 3;
        out[O_BOX + ((size_t)b * MAX_DET + j) * 4 + c] =
            g_dbox[((size_t)b * 4 + c) * A_TOT + s_idx[j]];
    }
    for (int j = t; j < MAX_DET; j += 1024) {
        out[O_SCORE + b * MAX_DET + j] = s_val[j];
        out[O_CLS   + b * MAX_DET + j] = (float)g_cls[b * A_TOT + s_idx[j]];
    }
    for (int e = t; e < MAX_DET * NKPT; e += 1024) {
        int j = e / NKPT, nk = e - j * NKPT;
        out[O_KPT + ((size_t)b * MAX_DET + j) * NKPT + nk] =
            g_kpts[((size_t)b * NKPT + nk) * A_TOT + s_idx[j]];
    }
}

// ---------------------------------------------------------------------------
extern "C" void kernel_launch(void* const* d_in, const int* in_sizes, int n_in,
                              void* d_out, int out_size)
{
    cudaFuncSetAttribute(gemm_tc, cudaFuncAttributeMaxDynamicSharedMemorySize, SMEM_BYTES);

    pack_k<<<(229376 + 255) / 256, 256>>>(
        (const float*)d_in[3],  (const float*)d_in[4],
        (const float*)d_in[5],  (const float*)d_in[6],
        (const float*)d_in[7],  (const float*)d_in[8],
        (const float*)d_in[9],  (const float*)d_in[10],
        (const float*)d_in[11], (const float*)d_in[12],
        (const float*)d_in[13], (const float*)d_in[14],
        (const float*)d_in[15], (const float*)d_in[16],
        (const float*)d_in[17], (const float*)d_in[18],
        (const float*)d_in[19], (const float*)d_in[20]);

    gemm_tc<<<1072, 512, SMEM_BYTES>>>((const float*)d_in[0],
                                       (const float*)d_in[1],
                                       (const float*)d_in[2]);

    topk_k<<<BS, 1024>>>((float*)d_out);
}

// round 8
// speedup vs baseline: 4.1604x; 1.1386x over previous
#include <cuda_runtime.h>
#include <cuda_fp16.h>
#include <math.h>
#include <stdint.h>

#define BS 16
#define NCLS 80
#define NKPT 51
#define A_TOT 8400
#define MAX_DET 100
#define CONF 0.25f

// output layout (floats)
#define O_NUM   0
#define O_BOX   16
#define O_SCORE 6416
#define O_CLS   8016
#define O_KPT   9616

// device scratch
__device__ __align__(16) __half g_wh[229376];   // [s][n=256][k], hi part
__device__ __align__(16) __half g_wl[229376];   // lo part
__device__ float g_bias[3 * 256];
__device__ float g_dbox[(size_t)BS * 4 * A_TOT];
__device__ float g_kpts[(size_t)BS * NKPT * A_TOT];
__device__ float g_maxs[BS * A_TOT];
__device__ int   g_cls[BS * A_TOT];

// ---------------------------------------------------------------------------
// Pack (single launch): split weights into fp16 hi/lo + bias.
// ---------------------------------------------------------------------------
__global__ void pack_k(const float* __restrict__ w20, const float* __restrict__ b20,
                       const float* __restrict__ w21, const float* __restrict__ b21,
                       const float* __restrict__ w22, const float* __restrict__ b22,
                       const float* __restrict__ w30, const float* __restrict__ b30,
                       const float* __restrict__ w31, const float* __restrict__ b31,
                       const float* __restrict__ w32, const float* __restrict__ b32,
                       const float* __restrict__ w40, const float* __restrict__ b40,
                       const float* __restrict__ w41, const float* __restrict__ b41,
                       const float* __restrict__ w42, const float* __restrict__ b42)
{
    int gidx = blockIdx.x * blockDim.x + threadIdx.x;
    if (gidx >= 229376) return;
    int s, idx, C;
    if (gidx < 32768)       { s = 0; idx = gidx;          C = 128; }
    else if (gidx < 98304)  { s = 1; idx = gidx - 32768;  C = 256; }
    else                    { s = 2; idx = gidx - 98304;  C = 512; }
    const float* w2 = (s == 0) ? w20 : (s == 1) ? w21 : w22;
    const float* b2 = (s == 0) ? b20 : (s == 1) ? b21 : b22;
    const float* w3 = (s == 0) ? w30 : (s == 1) ? w31 : w32;
    const float* b3 = (s == 0) ? b30 : (s == 1) ? b31 : b32;
    const float* w4 = (s == 0) ? w40 : (s == 1) ? w41 : w42;
    const float* b4 = (s == 0) ? b40 : (s == 1) ? b41 : b42;

    int n = idx / C;
    int k = idx - n * C;
    float v = 0.f;
    if (n < 64)        v = w2[n * C + k];
    else if (n < 144)  v = w3[(n - 64) * C + k];
    else if (n < 195)  v = w4[(n - 144) * C + k];
    __half h = __float2half_rn(v);
    g_wh[gidx] = h;
    g_wl[gidx] = __float2half_rn(v - __half2float(h));
    if (k == 0) {
        float bb = 0.f;
        if (n < 64)        bb = b2[n];
        else if (n < 144)  bb = b3[n - 64];
        else if (n < 195)  bb = b4[n - 144];
        g_bias[s * 256 + n] = bb;
    }
}

// ---------------------------------------------------------------------------
__device__ __forceinline__ void mma_f16(float* c, const uint32_t* a,
                                        uint32_t b0, uint32_t b1)
{
    asm volatile(
        "mma.sync.aligned.m16n8k16.row.col.f32.f16.f16.f32 "
        "{%0,%1,%2,%3}, {%4,%5,%6,%7}, {%8,%9}, {%0,%1,%2,%3};"
        : "+f"(c[0]), "+f"(c[1]), "+f"(c[2]), "+f"(c[3])
        : "r"(a[0]), "r"(a[1]), "r"(a[2]), "r"(a[3]), "r"(b0), "r"(b1));
}

__device__ __forceinline__ void ldm_x4(uint32_t* r, uint32_t addr)
{
    asm volatile("ldmatrix.sync.aligned.m8n8.x4.shared.b16 {%0,%1,%2,%3}, [%4];"
                 : "=r"(r[0]), "=r"(r[1]), "=r"(r[2]), "=r"(r[3]) : "r"(addr));
}

// split v into (hi, fp16-exact via mantissa mask) + (lo fp16), packed converts
__device__ __forceinline__ void split2(float v0, float v1, uint32_t& hh, uint32_t& ll)
{
    float h0 = __uint_as_float(__float_as_uint(v0) & 0xFFFFE000u);
    float h1 = __uint_as_float(__float_as_uint(v1) & 0xFFFFE000u);
    __half2 hp = __float22half2_rn(make_float2(h0, h1));
    __half2 lp = __float22half2_rn(make_float2(v0 - h0, v1 - h1));
    hh = *(uint32_t*)&hp;
    ll = *(uint32_t*)&lp;
}

__device__ __forceinline__ float dfl16(const float* v) {
    float mx = v[0];
#pragma unroll
    for (int i = 1; i < 16; i++) mx = fmaxf(mx, v[i]);
    float s = 0.f, w = 0.f;
#pragma unroll
    for (int i = 0; i < 16; i++) {
        float e = expf(v[i] - mx);
        s += e;
        w += e * (float)i;
    }
    return w / s;
}

// smem word layout, row stride 20 words (40 halves).
// per stage: A_HI 64x20=1280, A_LO 1280, B_HI 208x20=4160, B_LO 4160 -> 10880
// D tile (64 x 201 fp32 = 12864 words) aliases the two stages after mainloop.
#define ST_WORDS 10880
#define A_LO_W   1280
#define B_HI_W   2560
#define B_LO_W   6720
#define SM_D     0
#define SM_BIAS  21760
#define SM_WORDS 22016
#define SMEM_BYTES (SM_WORDS * 4)      // 88064

// ---------------------------------------------------------------------------
// Fused GEMM (split-fp16 mma.sync, ldmatrix, 2-stage cp.async) + decode.
// M=64 anchors x N=208 outs per CTA, 256 threads = 8 warps, 2 CTAs/SM.
// wm = wid&1 (32 rows), wn = wid>>1: wn 0..2 -> 3 n16 tiles, wn 3 -> 4 tiles.
// CTA order: s2 (16 chunks) first, then s1, then s0 (longest-first).
// ---------------------------------------------------------------------------
__global__ void __launch_bounds__(256, 2) gemm_tc(const float* __restrict__ x0,
                                                  const float* __restrict__ x1,
                                                  const float* __restrict__ x2)
{
    extern __shared__ uint32_t sm[];
    float* smf = (float*)sm;

    int bid = blockIdx.x;
    int s, rel;
    if (bid < 112)      { s = 2; rel = bid; }
    else if (bid < 512) { s = 1; rel = bid - 112; }
    else                { s = 0; rel = bid - 512; }
    const int tpbA[3]  = {100, 25, 7};
    const int CsA[3]   = {128, 256, 512};
    const int HWA[3]   = {6400, 1600, 400};
    const int soffA[3] = {0, 6400, 8000};
    const int WA[3]    = {80, 40, 20};
    const int woffA[3] = {0, 32768, 98304};
    const float strA[3] = {8.f, 16.f, 32.f};

    const int C = CsA[s], HW = HWA[s], W = WA[s];
    const float stride = strA[s];
    const int b    = rel / tpbA[s];
    const int tile = rel - b * tpbA[s];
    const int pos0 = tile * 64;
    const int valid = min(64, HW - pos0);

    const float* xsel = (s == 0) ? x0 : (s == 1) ? x1 : x2;
    const float* xb = xsel + (size_t)b * C * HW + pos0;
    const __half* wh = g_wh + woffA[s];
    const __half* wl = g_wl + woffA[s];

    const int t = threadIdx.x;
    const int lane = t & 31;
    const int wid = t >> 5;
    const int wm = wid & 1;
    const int wn = wid >> 1;
    const int ntiles = (wn < 3) ? 3 : 4;
    const int ncol0  = (wn < 3) ? wn * 48 : 144;

    const uint32_t smb = (uint32_t)__cvta_generic_to_shared(sm);

    if (t < 256) smf[SM_BIAS + t] = g_bias[s * 256 + t];

    float acc0[8][4];   // mt=0 accumulators, index ntp*2+h
    float acc1[8][4];   // mt=1
#pragma unroll
    for (int i = 0; i < 8; i++)
#pragma unroll
        for (int j = 0; j < 4; j++) { acc0[i][j] = 0.f; acc1[i][j] = 0.f; }

    const int am   = t & 63;
    const int akp0 = t >> 6;
    const int bn   = t >> 2;
    const int boff = t & 3;

    const int nkt = C >> 5;

    // ---- prologue: chunk 0 ----
    {
#pragma unroll
        for (int i = 0; i < 4; i++) {
            const int n = bn + i * 64;
            if (n < 208) {
                const uint32_t dsth = smb + (B_HI_W + n * 20 + boff * 4) * 4;
                const uint32_t dstl = smb + (B_LO_W + n * 20 + boff * 4) * 4;
                asm volatile("cp.async.cg.shared.global [%0], [%1], 16;"
                             :: "r"(dsth), "l"(wh + (size_t)n * C + boff * 8) : "memory");
                asm volatile("cp.async.cg.shared.global [%0], [%1], 16;"
                             :: "r"(dstl), "l"(wl + (size_t)n * C + boff * 8) : "memory");
            }
        }
        asm volatile("cp.async.commit_group;" ::: "memory");
        float v[8];
#pragma unroll
        for (int j = 0; j < 8; j++)
            v[j] = (am < valid) ? xb[(size_t)(akp0 * 8 + j) * HW + am] : 0.f;
        uint32_t hw4[4], lw4[4];
#pragma unroll
        for (int p = 0; p < 4; p++) split2(v[2*p], v[2*p+1], hw4[p], lw4[p]);
        *(uint4*)&sm[am * 20 + akp0 * 4]          = *(uint4*)hw4;
        *(uint4*)&sm[A_LO_W + am * 20 + akp0 * 4] = *(uint4*)lw4;
    }

    for (int kt = 0; kt < nkt; kt++) {
        const int st = (kt & 1) ? ST_WORDS : 0;
        asm volatile("cp.async.wait_group 0;" ::: "memory");
        __syncthreads();

        float apre[8];
        const bool pf = (kt + 1 < nkt);
        const int stn = ((kt + 1) & 1) ? ST_WORDS : 0;
        if (pf) {
            const int c1 = (kt + 1) << 5;
#pragma unroll
            for (int i = 0; i < 4; i++) {
                const int n = bn + i * 64;
                if (n < 208) {
                    const uint32_t dsth = smb + (stn + B_HI_W + n * 20 + boff * 4) * 4;
                    const uint32_t dstl = smb + (stn + B_LO_W + n * 20 + boff * 4) * 4;
                    asm volatile("cp.async.cg.shared.global [%0], [%1], 16;"
                                 :: "r"(dsth), "l"(wh + (size_t)n * C + c1 + boff * 8) : "memory");
                    asm volatile("cp.async.cg.shared.global [%0], [%1], 16;"
                                 :: "r"(dstl), "l"(wl + (size_t)n * C + c1 + boff * 8) : "memory");
                }
            }
            asm volatile("cp.async.commit_group;" ::: "memory");
#pragma unroll
            for (int j = 0; j < 8; j++)
                apre[j] = (am < valid) ? xb[(size_t)(c1 + akp0 * 8 + j) * HW + am] : 0.f;
        }

        // ---- compute current chunk ----
#pragma unroll
        for (int k16 = 0; k16 < 2; k16++) {
            uint32_t ah[2][4], al[2][4];
            const uint32_t acol = k16 * 32 + (lane >> 4) * 16;
#pragma unroll
            for (int mt = 0; mt < 2; mt++) {
                const int row = wm * 32 + mt * 16 + (lane & 15);
                const uint32_t ba = smb + (st + row * 20) * 4 + acol;
                ldm_x4(ah[mt], ba);
                ldm_x4(al[mt], ba + A_LO_W * 4);
            }
            const int brow = (lane & 7) + ((lane >> 4) << 3);
            const uint32_t bcol = ((lane >> 3) & 1) * 16 + k16 * 32;
#pragma unroll
            for (int ntp = 0; ntp < 4; ntp++) {
                if (ntp >= ntiles) break;
                const int nb = ncol0 + ntp * 16 + brow;
                uint32_t bh[4], bl[4];
                const uint32_t bbp = smb + (st + B_HI_W + nb * 20) * 4 + bcol;
                ldm_x4(bh, bbp);
                ldm_x4(bl, bbp + (B_LO_W - B_HI_W) * 4);
#pragma unroll
                for (int h = 0; h < 2; h++) {
                    const int g = ntp * 2 + h;
                    mma_f16(acc0[g], ah[0], bh[2*h], bh[2*h+1]);
                    mma_f16(acc0[g], ah[0], bl[2*h], bl[2*h+1]);
                    mma_f16(acc0[g], al[0], bh[2*h], bh[2*h+1]);
                    mma_f16(acc1[g], ah[1], bh[2*h], bh[2*h+1]);
                    mma_f16(acc1[g], ah[1], bl[2*h], bl[2*h+1]);
                    mma_f16(acc1[g], al[1], bh[2*h], bh[2*h+1]);
                }
            }
        }

        if (pf) {
            uint32_t hw4[4], lw4[4];
#pragma unroll
            for (int p = 0; p < 4; p++) split2(apre[2*p], apre[2*p+1], hw4[p], lw4[p]);
            *(uint4*)&sm[stn + am * 20 + akp0 * 4]          = *(uint4*)hw4;
            *(uint4*)&sm[stn + A_LO_W + am * 20 + akp0 * 4] = *(uint4*)lw4;
        }
    }
    __syncthreads();

    // ---- stage D tile (cols 0..199, stride 201) ----
#pragma unroll
    for (int ntp = 0; ntp < 4; ntp++) {
        if (ntp >= ntiles) break;
#pragma unroll
        for (int h = 0; h < 2; h++) {
            const int n = ncol0 + ntp * 16 + h * 8 + (lane & 3) * 2;
            if (n >= 200) continue;
            const int g = ntp * 2 + h;
#pragma unroll
            for (int mt = 0; mt < 2; mt++) {
                const int r = wm * 32 + mt * 16 + (lane >> 2);
                const float* c = (mt == 0) ? acc0[g] : acc1[g];
                smf[SM_D + r * 201 + n]           = c[0];
                smf[SM_D + r * 201 + n + 1]       = c[1];
                smf[SM_D + (r + 8) * 201 + n]     = c[2];
                smf[SM_D + (r + 8) * 201 + n + 1] = c[3];
            }
        }
    }
    __syncthreads();

    // ---- decode epilogue: 4 threads per anchor (64 x 4 = 256) ----
    {
        const int ar  = t >> 2;
        const int sub = t & 3;
        const bool ok = ar < valid;
        const int pos = pos0 + ar;
        const int a_g = soffA[s] + pos;
        const int py = pos / W, px = pos - py * W;
        const float gx = px + 0.5f, gy = py + 0.5f;
        const float* Dr = smf + SM_D + ar * 201;
        const float* bi = smf + SM_BIAS;
        const unsigned msk = 0xffffffffu;

        float v16[16];
#pragma unroll
        for (int i = 0; i < 16; i++) v16[i] = Dr[sub * 16 + i] + bi[sub * 16 + i];
        float d = dfl16(v16);
        const float d0 = __shfl_sync(msk, d, 0, 4);
        const float d1 = __shfl_sync(msk, d, 1, 4);
        const float d2 = __shfl_sync(msk, d, 2, 4);
        const float d3 = __shfl_sync(msk, d, 3, 4);
        if (ok && sub == 0) {
            float x1 = gx - d0, y1 = gy - d1;
            float x2 = gx + d2, y2 = gy + d3;
            g_dbox[((size_t)b * 4 + 0) * A_TOT + a_g] = (x1 + x2) * 0.5f * stride;
            g_dbox[((size_t)b * 4 + 1) * A_TOT + a_g] = (y1 + y2) * 0.5f * stride;
            g_dbox[((size_t)b * 4 + 2) * A_TOT + a_g] = (x2 - x1) * stride;
            g_dbox[((size_t)b * 4 + 3) * A_TOT + a_g] = (y2 - y1) * stride;
        }

        float best = -INFINITY; int bcls = 0;
#pragma unroll
        for (int c = 0; c < 20; c++) {
            const int cc = sub * 20 + c;
            float v = Dr[64 + cc] + bi[64 + cc];
            if (v > best) { best = v; bcls = cc; }
        }
#pragma unroll
        for (int o = 2; o > 0; o >>= 1) {
            float v2 = __shfl_down_sync(msk, best, o, 4);
            int   i2 = __shfl_down_sync(msk, bcls, o, 4);
            if (v2 > best || (v2 == best && i2 < bcls)) { best = v2; bcls = i2; }
        }
        if (ok && sub == 0) {
            g_maxs[b * A_TOT + a_g] = 1.f / (1.f + expf(-best));
            g_cls[b * A_TOT + a_g]  = bcls;
        }

        if (ok) {
            for (int nk = sub; nk < NKPT; nk += 4) {
                float v = Dr[144 + nk] + bi[144 + nk];
                const int comp = nk % 3;
                float o = (comp == 0) ? (v * 2.f + (gx - 0.5f)) * stride
                        : (comp == 1) ? (v * 2.f + (gy - 0.5f)) * stride
                                      : 1.f / (1.f + expf(-v));
                g_kpts[((size_t)b * NKPT + nk) * A_TOT + a_g] = o;
            }
        }
    }
}

// ---------------------------------------------------------------------------
// Per-batch top-100 via histogram threshold + bitonic sort of candidates.
// ---------------------------------------------------------------------------
#define NBIN 4096
#define CANDC 2048

__global__ void __launch_bounds__(1024) topk_k(float* __restrict__ out)
{
    __shared__ int hist[NBIN];
    __shared__ int coarse[256];
    __shared__ unsigned long long cand[CANDC];
    __shared__ int s_cnt, s_T;
    __shared__ int s_idx[MAX_DET];
    __shared__ float s_val[MAX_DET];

    const int b = blockIdx.x;
    const int t = threadIdx.x;
    const float* scores = g_maxs + b * A_TOT;

#pragma unroll
    for (int i = 0; i < NBIN / 1024; i++) hist[t + i * 1024] = 0;
#pragma unroll
    for (int i = 0; i < CANDC / 1024; i++) cand[t + i * 1024] = 0ull;
    if (t == 0) s_cnt = 0;
    __syncthreads();

    for (int i = t; i < A_TOT; i += 1024) {
        int bin = min(NBIN - 1, max(0, (int)(scores[i] * (float)NBIN)));
        atomicAdd(&hist[bin], 1);
    }
    __syncthreads();

    if (t < 256) {
        int sum = 0;
#pragma unroll
        for (int i = 0; i < 16; i++) sum += hist[t * 16 + i];
        coarse[t] = sum;
    }
    __syncthreads();

    if (t == 0) {
        int acc = 0, T = 0;
        int c;
        for (c = 255; c >= 0; c--) {
            if (acc + coarse[c] >= MAX_DET) break;
            acc += coarse[c];
        }
        if (c < 0) { T = 0; }
        else {
            for (int bin = c * 16 + 15; bin >= c * 16; bin--) {
                acc += hist[bin];
                if (acc >= MAX_DET) { T = bin; break; }
                if (bin == c * 16) T = bin;
            }
        }
        s_T = T;
    }
    __syncthreads();

    const int T = s_T;
    for (int i = t; i < A_TOT; i += 1024) {
        float v = scores[i];
        int bin = min(NBIN - 1, max(0, (int)(v * (float)NBIN)));
        if (bin >= T) {
            int pos = atomicAdd(&s_cnt, 1);
            if (pos < CANDC)
                cand[pos] = ((unsigned long long)__float_as_uint(v) << 32)
                          | (unsigned long long)(A_TOT - 1 - i);
        }
    }
    __syncthreads();

    for (int k = 2; k <= CANDC; k <<= 1) {
        for (int j = k >> 1; j > 0; j >>= 1) {
            int idx = ((t & ~(j - 1)) << 1) | (t & (j - 1));
            int ixj = idx | j;
            unsigned long long a = cand[idx], bb2 = cand[ixj];
            bool descBlk = ((idx & k) == 0);
            if ((a < bb2) == descBlk) { cand[idx] = bb2; cand[ixj] = a; }
            __syncthreads();
        }
    }

    if (t < MAX_DET) {
        unsigned long long key = cand[t];
        s_val[t] = __uint_as_float((uint32_t)(key >> 32));
        s_idx[t] = A_TOT - 1 - (int)(key & 0xFFFFFFFFull);
    }
    __syncthreads();

    if (t == 0) {
        int cnt = 0;
        for (int j = 0; j < MAX_DET; j++) cnt += (s_val[j] > CONF) ? 1 : 0;
        out[O_NUM + b] = (float)cnt;
    }
    for (int e = t; e < MAX_DET * 4; e += 1024) {
        int j = e >> 2, c = e & 3;
        out[O_BOX + ((size_t)b * MAX_DET + j) * 4 + c] =
            g_dbox[((size_t)b * 4 + c) * A_TOT + s_idx[j]];
    }
    for (int j = t; j < MAX_DET; j += 1024) {
        out[O_SCORE + b * MAX_DET + j] = s_val[j];
        out[O_CLS   + b * MAX_DET + j] = (float)g_cls[b * A_TOT + s_idx[j]];
    }
    for (int e = t; e < MAX_DET * NKPT; e += 1024) {
        int j = e / NKPT, nk = e - j * NKPT;
        out[O_KPT + ((size_t)b * MAX_DET + j) * NKPT + nk] =
            g_kpts[((size_t)b * NKPT + nk) * A_TOT + s_idx[j]];
    }
}

// ---------------------------------------------------------------------------
extern "C" void kernel_launch(void* const* d_in, const int* in_sizes, int n_in,
                              void* d_out, int out_size)
{
    cudaFuncSetAttribute(gemm_tc, cudaFuncAttributeMaxDynamicSharedMemorySize, SMEM_BYTES);

    pack_k<<<(229376 + 255) / 256, 256>>>(
        (const float*)d_in[3],  (const float*)d_in[4],
        (const float*)d_in[5],  (const float*)d_in[6],
        (const float*)d_in[7],  (const float*)d_in[8],
        (const float*)d_in[9],  (const float*)d_in[10],
        (const float*)d_in[11], (const float*)d_in[12],
        (const float*)d_in[13], (const float*)d_in[14],
        (const float*)d_in[15], (const float*)d_in[16],
        (const float*)d_in[17], (const float*)d_in[18],
        (const float*)d_in[19], (const float*)d_in[20]);

    gemm_tc<<<2112, 256, SMEM_BYTES>>>((const float*)d_in[0],
                                       (const float*)d_in[1],
                                       (const float*)d_in[2]);

    topk_k<<<BS, 1024>>>((float*)d_out);
}